// round 2
// baseline (speedup 1.0000x reference)
#include <cuda_runtime.h>
#include <math.h>

#define Sn 256
#define Bn 128
#define En 256
#define Hn 512
#define Tn 18
#define G4n 2048

// ---------------- scratch (device globals; no cudaMalloc allowed) ----------------
__device__ float d_x[Sn * Bn * En];            //  33.5 MB  embedded input [s][b][e]
__device__ float d_xp_f[Sn * Bn * G4n];        // 268 MB    input projection, fwd dir
__device__ float d_xp_b[Sn * Bn * G4n];        // 268 MB    input projection, bwd dir
__device__ float d_out0[Sn * Bn * 2 * Hn];     // 134 MB    layer0 output [s][b][2H]
__device__ float d_out1[Sn * Bn * 2 * Hn];     // 134 MB    layer1 output
__device__ float d_hfc[Sn * Bn * Hn];          //  67 MB    fc+relu output
__device__ float d_em[Sn * Bn * Tn];           //  emissions [s][b][t]
__device__ float d_hst[2][2][Bn * Hn];         //  h state [dir][parity]
__device__ float d_cst[2][Bn * Hn];            //  c state [dir]
__device__ float d_num[Bn];
__device__ float d_den[Bn];

// ---------------- embedding lookup (padding_idx=0 -> zeros) ----------------
__global__ void embed_kernel(const int* __restrict__ ids, const float* __restrict__ emb)
{
    int n = blockIdx.x;          // n = s*B + b
    int s = n >> 7;
    int b = n & 127;
    int id = ids[b * Sn + s];
    float4 v;
    if (id == 0) v = make_float4(0.f, 0.f, 0.f, 0.f);
    else         v = ((const float4*)(emb + (size_t)id * En))[threadIdx.x];
    ((float4*)(d_x + (size_t)n * En))[threadIdx.x] = v;
}

// ---------------- generic NT SGEMM: C[M,N] = A[M,K] * W[N,K]^T + bias, opt relu ----
// BM=128, BN=64, BK=16, 256 threads, 8x4 per thread. M%128==0, N%64==0, K%16==0.
__global__ __launch_bounds__(256) void sgemm_nt(
    const float* __restrict__ A, const float* __restrict__ W,
    const float* __restrict__ bias, float* __restrict__ C,
    int M, int N, int K, int relu)
{
    __shared__ float As[16][132];
    __shared__ float Ws[16][68];
    int tid = threadIdx.x;
    int m0 = blockIdx.y * 128;
    int n0 = blockIdx.x * 64;
    int tx = tid & 15, ty = tid >> 4;

    float acc[8][4];
#pragma unroll
    for (int i = 0; i < 8; i++)
#pragma unroll
        for (int j = 0; j < 4; j++) acc[i][j] = 0.f;

    for (int k0 = 0; k0 < K; k0 += 16) {
#pragma unroll
        for (int i = 0; i < 2; i++) {
            int q = tid * 2 + i;
            int r = q >> 2, kq = q & 3;
            float4 v = *(const float4*)(A + (size_t)(m0 + r) * K + k0 + kq * 4);
            As[kq * 4 + 0][r] = v.x; As[kq * 4 + 1][r] = v.y;
            As[kq * 4 + 2][r] = v.z; As[kq * 4 + 3][r] = v.w;
        }
        {
            int r = tid >> 2, kq = tid & 3;
            float4 v = *(const float4*)(W + (size_t)(n0 + r) * K + k0 + kq * 4);
            Ws[kq * 4 + 0][r] = v.x; Ws[kq * 4 + 1][r] = v.y;
            Ws[kq * 4 + 2][r] = v.z; Ws[kq * 4 + 3][r] = v.w;
        }
        __syncthreads();
#pragma unroll
        for (int k = 0; k < 16; k++) {
            float4 a0 = *(const float4*)&As[k][ty * 8];
            float4 a1 = *(const float4*)&As[k][ty * 8 + 4];
            float4 w  = *(const float4*)&Ws[k][tx * 4];
            float a[8] = {a0.x, a0.y, a0.z, a0.w, a1.x, a1.y, a1.z, a1.w};
            float wv[4] = {w.x, w.y, w.z, w.w};
#pragma unroll
            for (int i = 0; i < 8; i++)
#pragma unroll
                for (int j = 0; j < 4; j++) acc[i][j] += a[i] * wv[j];
        }
        __syncthreads();
    }
#pragma unroll
    for (int i = 0; i < 8; i++) {
        size_t row = (size_t)(m0 + ty * 8 + i) * N;
#pragma unroll
        for (int j = 0; j < 4; j++) {
            int n = n0 + tx * 4 + j;
            float v = acc[i][j] + bias[n];
            if (relu) v = fmaxf(v, 0.f);
            C[row + n] = v;
        }
    }
}

// ---------------- one LSTM timestep, both directions fused ----------------
// grid = (64 j-blocks, 2 dirs), 256 threads. Each thread: 4 b x (i,f,g,o) for one j.
// h double-buffered across launches (si parity) to avoid cross-block RAW.
__global__ __launch_bounds__(256) void lstm_step_kernel(
    const float* __restrict__ xpf, const float* __restrict__ xpb,
    const float* __restrict__ whhf, const float* __restrict__ whhb,
    float* __restrict__ out, int si)
{
    int dir = blockIdx.y;
    const float* xp  = dir ? xpb : xpf;
    const float* whh = dir ? whhb : whhf;
    float* hin  = d_hst[dir][si & 1];
    float* hout = d_hst[dir][(si & 1) ^ 1];
    float* cst  = d_cst[dir];
    int t = dir ? (Sn - 1 - si) : si;
    int j0 = blockIdx.x * 8;

    __shared__ float hs[32][132];   // [k][b]
    __shared__ float ws[32][36];    // [k][gate*8 + jl]
    int tid = threadIdx.x;
    int jl = tid & 7, bg = tid >> 3;
    int b0v = bg * 4;
    int j = j0 + jl;

    float acc[4][4];
#pragma unroll
    for (int i = 0; i < 4; i++)
#pragma unroll
        for (int g = 0; g < 4; g++) acc[i][g] = 0.f;

    int wr = tid >> 3;              // 0..31: which whh row this thread loads
    int wgi = wr >> 3, wjl = wr & 7;
    const float* wrow = whh + (size_t)(wgi * Hn + j0 + wjl) * Hn;
    int wkq = tid & 7;

    for (int kt = 0; kt < Hn; kt += 32) {
#pragma unroll
        for (int i = 0; i < 4; i++) {
            int q = tid + i * 256;
            int bb = q >> 3, kq = q & 7;
            float4 v = *(const float4*)(hin + (size_t)bb * Hn + kt + kq * 4);
            hs[kq * 4 + 0][bb] = v.x; hs[kq * 4 + 1][bb] = v.y;
            hs[kq * 4 + 2][bb] = v.z; hs[kq * 4 + 3][bb] = v.w;
        }
        {
            float4 v = *(const float4*)(wrow + kt + wkq * 4);
            ws[wkq * 4 + 0][wr] = v.x; ws[wkq * 4 + 1][wr] = v.y;
            ws[wkq * 4 + 2][wr] = v.z; ws[wkq * 4 + 3][wr] = v.w;
        }
        __syncthreads();
#pragma unroll
        for (int k = 0; k < 32; k++) {
            float4 hv = *(const float4*)&hs[k][b0v];
            float w0 = ws[k][jl], w1 = ws[k][8 + jl], w2 = ws[k][16 + jl], w3 = ws[k][24 + jl];
            acc[0][0] += hv.x * w0; acc[0][1] += hv.x * w1; acc[0][2] += hv.x * w2; acc[0][3] += hv.x * w3;
            acc[1][0] += hv.y * w0; acc[1][1] += hv.y * w1; acc[1][2] += hv.y * w2; acc[1][3] += hv.y * w3;
            acc[2][0] += hv.z * w0; acc[2][1] += hv.z * w1; acc[2][2] += hv.z * w2; acc[2][3] += hv.z * w3;
            acc[3][0] += hv.w * w0; acc[3][1] += hv.w * w1; acc[3][2] += hv.w * w2; acc[3][3] += hv.w * w3;
        }
        __syncthreads();
    }

#pragma unroll
    for (int bi = 0; bi < 4; bi++) {
        int b = b0v + bi;
        size_t xb = ((size_t)t * Bn + b) * G4n;
        float gi = acc[bi][0] + xp[xb + 0 * Hn + j];
        float gf = acc[bi][1] + xp[xb + 1 * Hn + j];
        float gg = acc[bi][2] + xp[xb + 2 * Hn + j];
        float go = acc[bi][3] + xp[xb + 3 * Hn + j];
        float ig = 1.f / (1.f + expf(-gi));
        float fg = 1.f / (1.f + expf(-gf));
        float og = 1.f / (1.f + expf(-go));
        float cc = fg * cst[b * Hn + j] + ig * tanhf(gg);
        float hh = og * tanhf(cc);
        cst[b * Hn + j] = cc;
        hout[b * Hn + j] = hh;
        out[((size_t)t * Bn + b) * (2 * Hn) + dir * Hn + j] = hh;
    }
}

// ---------------- emissions: em[row][t] = hfc[row] . cls_w[t] + cls_b[t] ----------
__global__ void emissions_kernel(const float* __restrict__ hfc,
                                 const float* __restrict__ cls_w,
                                 const float* __restrict__ cls_b)
{
    int warp = blockIdx.x * 8 + (threadIdx.x >> 5);   // row = s*B + b
    int lane = threadIdx.x & 31;
    const float* hrow = hfc + (size_t)warp * Hn;
    float hv[16];
#pragma unroll
    for (int q = 0; q < 16; q++) hv[q] = hrow[lane + q * 32];
    for (int tt = 0; tt < Tn; tt++) {
        const float* wr = cls_w + tt * Hn;
        float s = 0.f;
#pragma unroll
        for (int q = 0; q < 16; q++) s += hv[q] * wr[lane + q * 32];
#pragma unroll
        for (int o = 16; o > 0; o >>= 1) s += __shfl_xor_sync(0xffffffffu, s, o);
        if (lane == 0) d_em[(size_t)warp * Tn + tt] = s + cls_b[tt];
    }
}

// ---------------- CRF gold-path score (numerator) ----------------
__global__ void crf_num_kernel(const int* __restrict__ ids, const int* __restrict__ tags,
                               const float* __restrict__ trans,
                               const float* __restrict__ start_t, const float* __restrict__ end_t)
{
    int b = threadIdx.x;   // 128 threads
    int tg0 = tags[b * Sn + 0];
    float score = start_t[tg0] + d_em[(size_t)b * Tn + tg0];
    int cnt = (ids[b * Sn + 0] != 0) ? 1 : 0;
    int prev = tg0;
    for (int s = 1; s < Sn; s++) {
        int tg = tags[b * Sn + s];
        if (ids[b * Sn + s] != 0) {
            score += trans[prev * Tn + tg] + d_em[((size_t)s * Bn + b) * Tn + tg];
            cnt++;
        }
        prev = tg;
    }
    int se = cnt - 1; if (se < 0) se = 0;   // JAX gather clamps
    d_num[b] = score + end_t[tags[b * Sn + se]];
}

// ---------------- CRF forward algorithm (denominator), block per batch ----------
__global__ void crf_fwd_kernel(const int* __restrict__ ids,
                               const float* __restrict__ trans,
                               const float* __restrict__ start_t,
                               const float* __restrict__ end_t)
{
    int b = blockIdx.x;
    int j = threadIdx.x;   // 32 threads, j<18 active
    __shared__ float alpha[Tn];
    __shared__ float tr[Tn * Tn];
    for (int idx = j; idx < Tn * Tn; idx += 32) tr[idx] = trans[idx];
    if (j < Tn) alpha[j] = start_t[j] + d_em[(size_t)b * Tn + j];
    __syncthreads();
    for (int s = 1; s < Sn; s++) {
        bool m = ids[b * Sn + s] != 0;     // uniform across block
        float ns = 0.f;
        if (m && j < Tn) {
            float mx = -1e30f;
#pragma unroll
            for (int i = 0; i < Tn; i++) mx = fmaxf(mx, alpha[i] + tr[i * Tn + j]);
            float sum = 0.f;
#pragma unroll
            for (int i = 0; i < Tn; i++) sum += expf(alpha[i] + tr[i * Tn + j] - mx);
            ns = mx + logf(sum) + d_em[((size_t)s * Bn + b) * Tn + j];
        }
        __syncthreads();
        if (m && j < Tn) alpha[j] = ns;
        __syncthreads();
    }
    if (j == 0) {
        float mx = -1e30f;
        for (int i = 0; i < Tn; i++) mx = fmaxf(mx, alpha[i] + end_t[i]);
        float sum = 0.f;
        for (int i = 0; i < Tn; i++) sum += expf(alpha[i] + end_t[i] - mx);
        d_den[b] = mx + logf(sum);
    }
}

// ---------------- final: out = mean(num - den) ----------------
__global__ void final_kernel(float* __restrict__ out)
{
    int tid = threadIdx.x;   // 128
    __shared__ float sm[128];
    sm[tid] = d_num[tid] - d_den[tid];
    __syncthreads();
    for (int o = 64; o > 0; o >>= 1) {
        if (tid < o) sm[tid] += sm[tid + o];
        __syncthreads();
    }
    if (tid == 0) out[0] = sm[0] / 128.f;
}

// ---------------- launch ----------------
extern "C" void kernel_launch(void* const* d_in, const int* in_sizes, int n_in,
                              void* d_out, int out_size)
{
    (void)in_sizes; (void)n_in; (void)out_size;
    const int*   ids      = (const int*)d_in[0];
    const int*   tags     = (const int*)d_in[1];
    const float* emb      = (const float*)d_in[2];
    const float* w_ih_l0f = (const float*)d_in[3];
    const float* w_hh_l0f = (const float*)d_in[4];
    const float* b_l0f    = (const float*)d_in[5];
    const float* w_ih_l0b = (const float*)d_in[6];
    const float* w_hh_l0b = (const float*)d_in[7];
    const float* b_l0b    = (const float*)d_in[8];
    const float* w_ih_l1f = (const float*)d_in[9];
    const float* w_hh_l1f = (const float*)d_in[10];
    const float* b_l1f    = (const float*)d_in[11];
    const float* w_ih_l1b = (const float*)d_in[12];
    const float* w_hh_l1b = (const float*)d_in[13];
    const float* b_l1b    = (const float*)d_in[14];
    const float* fc_w     = (const float*)d_in[15];
    const float* fc_b     = (const float*)d_in[16];
    const float* cls_w    = (const float*)d_in[17];
    const float* cls_b    = (const float*)d_in[18];
    const float* trans    = (const float*)d_in[19];
    const float* start_t  = (const float*)d_in[20];
    const float* end_t    = (const float*)d_in[21];
    float* out = (float*)d_out;

    float *px, *pxf, *pxb, *pout0, *pout1, *phfc, *phst, *pcst;
    cudaGetSymbolAddress((void**)&px,    d_x);
    cudaGetSymbolAddress((void**)&pxf,   d_xp_f);
    cudaGetSymbolAddress((void**)&pxb,   d_xp_b);
    cudaGetSymbolAddress((void**)&pout0, d_out0);
    cudaGetSymbolAddress((void**)&pout1, d_out1);
    cudaGetSymbolAddress((void**)&phfc,  d_hfc);
    cudaGetSymbolAddress((void**)&phst,  d_hst);
    cudaGetSymbolAddress((void**)&pcst,  d_cst);

    embed_kernel<<<Sn * Bn, 64>>>(ids, emb);

    dim3 g0(G4n / 64, (Sn * Bn) / 128);
    sgemm_nt<<<g0, 256>>>(px, w_ih_l0f, b_l0f, pxf, Sn * Bn, G4n, En, 0);
    sgemm_nt<<<g0, 256>>>(px, w_ih_l0b, b_l0b, pxb, Sn * Bn, G4n, En, 0);

    cudaMemsetAsync(phst, 0, sizeof(d_hst), 0);
    cudaMemsetAsync(pcst, 0, sizeof(d_cst), 0);

    dim3 gl(Hn / 8, 2);
    for (int s = 0; s < Sn; s++)
        lstm_step_kernel<<<gl, 256>>>(pxf, pxb, w_hh_l0f, w_hh_l0b, pout0, s);

    sgemm_nt<<<g0, 256>>>(pout0, w_ih_l1f, b_l1f, pxf, Sn * Bn, G4n, 2 * Hn, 0);
    sgemm_nt<<<g0, 256>>>(pout0, w_ih_l1b, b_l1b, pxb, Sn * Bn, G4n, 2 * Hn, 0);

    cudaMemsetAsync(phst, 0, sizeof(d_hst), 0);
    cudaMemsetAsync(pcst, 0, sizeof(d_cst), 0);

    for (int s = 0; s < Sn; s++)
        lstm_step_kernel<<<gl, 256>>>(pxf, pxb, w_hh_l1f, w_hh_l1b, pout1, s);

    dim3 gfc(Hn / 64, (Sn * Bn) / 128);
    sgemm_nt<<<gfc, 256>>>(pout1, fc_w, fc_b, phfc, Sn * Bn, Hn, 2 * Hn, 1);

    emissions_kernel<<<(Sn * Bn) / 8, 256>>>(phfc, cls_w, cls_b);
    crf_num_kernel<<<1, Bn>>>(ids, tags, trans, start_t, end_t);
    crf_fwd_kernel<<<Bn, 32>>>(ids, trans, start_t, end_t);
    final_kernel<<<1, Bn>>>(out);
}

// round 3
// speedup vs baseline: 1.6438x; 1.6438x over previous
#include <cuda_runtime.h>
#include <math.h>

#define Sn 256
#define Bn 128
#define En 256
#define Hn 512
#define Tn 18
#define G4n 2048

// ---------------- scratch (device globals; no cudaMalloc allowed) ----------------
__device__ float d_x[Sn * Bn * En];
__device__ float d_xp_f[Sn * Bn * G4n];        // layout [t][g*512+j][b]
__device__ float d_xp_b[Sn * Bn * G4n];        // layout [t][g*512+j][b]
__device__ float d_out0[Sn * Bn * 2 * Hn];     // [t][b][2H]
__device__ float d_out1[Sn * Bn * 2 * Hn];
__device__ float d_hfc[Sn * Bn * Hn];
__device__ float d_em[Sn * Bn * Tn];
__device__ float d_hst[2][2][Bn * Hn];         // h state [dir][parity][b*H+j]
__device__ float d_num[Bn];
__device__ float d_den[Bn];
__device__ unsigned g_cnt[2];
__device__ volatile unsigned g_gen[2];

// ---------------- packed f32x2 helpers (B300: FFMA2 = 2x FFMA throughput) -------
__device__ __forceinline__ unsigned long long ffma2(unsigned long long a,
                                                    unsigned long long b,
                                                    unsigned long long c) {
    unsigned long long d;
    asm("fma.rn.f32x2 %0, %1, %2, %3;" : "=l"(d) : "l"(a), "l"(b), "l"(c));
    return d;
}
__device__ __forceinline__ unsigned long long pk2(float x, float y) {
    unsigned long long r;
    asm("mov.b64 %0, {%1, %2};" : "=l"(r) : "f"(x), "f"(y));
    return r;
}
__device__ __forceinline__ float2 up2(unsigned long long v) {
    float2 r;
    asm("mov.b64 {%0, %1}, %2;" : "=f"(r.x), "=f"(r.y) : "l"(v));
    return r;
}

// ---------------- embedding lookup (padding_idx=0 -> zeros) ----------------
__global__ void embed_kernel(const int* __restrict__ ids, const float* __restrict__ emb)
{
    int n = blockIdx.x;          // n = s*B + b
    int s = n >> 7;
    int b = n & 127;
    int id = ids[b * Sn + s];
    float4 v;
    if (id == 0) v = make_float4(0.f, 0.f, 0.f, 0.f);
    else         v = ((const float4*)(emb + (size_t)id * En))[threadIdx.x];
    ((float4*)(d_x + (size_t)n * En))[threadIdx.x] = v;
}

// ---------------- SGEMM (NT) with f32x2: C = A[M,K] * W[N,K]^T + bias -----------
// BM=128, BN=128, BK=16, 256 threads, 8x8 per thread (n packed in f32x2 pairs).
// transT=0: C row-major [M][N].  transT=1: C layout [t=by][n][b] (b innermost).
__global__ __launch_bounds__(256) void sgemm_nt2(
    const float* __restrict__ A, const float* __restrict__ W,
    const float* __restrict__ bias, float* __restrict__ C,
    int N, int K, int relu, int transT)
{
    __shared__ float As[16][132];
    __shared__ float Bs[16][132];
    int tid = threadIdx.x;
    int tx = tid & 15, ty = tid >> 4;
    int m0 = blockIdx.y << 7, n0 = blockIdx.x << 7;

    unsigned long long acc[8][4];
#pragma unroll
    for (int i = 0; i < 8; i++)
#pragma unroll
        for (int j = 0; j < 4; j++) acc[i][j] = 0ull;

    for (int k0 = 0; k0 < K; k0 += 16) {
#pragma unroll
        for (int i = 0; i < 2; i++) {
            int q = tid + i * 256;
            int m = q >> 2, kq = q & 3;
            float4 v = *(const float4*)(A + (size_t)(m0 + m) * K + k0 + kq * 4);
            As[kq * 4 + 0][m] = v.x; As[kq * 4 + 1][m] = v.y;
            As[kq * 4 + 2][m] = v.z; As[kq * 4 + 3][m] = v.w;
            float4 w = *(const float4*)(W + (size_t)(n0 + m) * K + k0 + kq * 4);
            Bs[kq * 4 + 0][m] = w.x; Bs[kq * 4 + 1][m] = w.y;
            Bs[kq * 4 + 2][m] = w.z; Bs[kq * 4 + 3][m] = w.w;
        }
        __syncthreads();
#pragma unroll
        for (int k = 0; k < 16; k++) {
            float4 a0 = *(const float4*)&As[k][ty * 8];
            float4 a1 = *(const float4*)&As[k][ty * 8 + 4];
            ulonglong2 b0 = *(const ulonglong2*)&Bs[k][tx * 8];
            ulonglong2 b1 = *(const ulonglong2*)&Bs[k][tx * 8 + 4];
            unsigned long long ap[8];
            ap[0] = pk2(a0.x, a0.x); ap[1] = pk2(a0.y, a0.y);
            ap[2] = pk2(a0.z, a0.z); ap[3] = pk2(a0.w, a0.w);
            ap[4] = pk2(a1.x, a1.x); ap[5] = pk2(a1.y, a1.y);
            ap[6] = pk2(a1.z, a1.z); ap[7] = pk2(a1.w, a1.w);
#pragma unroll
            for (int mi = 0; mi < 8; mi++) {
                acc[mi][0] = ffma2(ap[mi], b0.x, acc[mi][0]);
                acc[mi][1] = ffma2(ap[mi], b0.y, acc[mi][1]);
                acc[mi][2] = ffma2(ap[mi], b1.x, acc[mi][2]);
                acc[mi][3] = ffma2(ap[mi], b1.y, acc[mi][3]);
            }
        }
        __syncthreads();
    }

    if (!transT) {
#pragma unroll
        for (int mi = 0; mi < 8; mi++) {
            size_t row = (size_t)(m0 + ty * 8 + mi) * N;
#pragma unroll
            for (int np = 0; np < 4; np++) {
                int n = n0 + tx * 8 + np * 2;
                float2 v = up2(acc[mi][np]);
                v.x += bias[n]; v.y += bias[n + 1];
                if (relu) { v.x = fmaxf(v.x, 0.f); v.y = fmaxf(v.y, 0.f); }
                *(float2*)&C[row + n] = v;
            }
        }
    } else {
        // C[t][n][b]: per m-block = one t (BM==Bn==128), b = m - m0
        size_t base = (size_t)blockIdx.y * ((size_t)N * Bn);
#pragma unroll
        for (int np = 0; np < 4; np++) {
#pragma unroll
            for (int e = 0; e < 2; e++) {
                int n = n0 + tx * 8 + np * 2 + e;
                float bv = bias[n];
                float v[8];
#pragma unroll
                for (int mi = 0; mi < 8; mi++) {
                    float2 p = up2(acc[mi][np]);
                    v[mi] = (e ? p.y : p.x) + bv;
                }
                float* dst = &C[base + (size_t)n * Bn + ty * 8];
                *(float4*)dst       = make_float4(v[0], v[1], v[2], v[3]);
                *(float4*)(dst + 4) = make_float4(v[4], v[5], v[6], v[7]);
            }
        }
    }
}

// ---------------- persistent BiLSTM layer kernel ----------------
// grid = 128 blocks (64 per dir), 256 threads. Block owns 8 h-columns (j-slice),
// Whh slice resident in smem, c in registers, per-dir global barrier each step.
// Dynamic smem: ws [512][36] (73728 B) + hs [64][132] (33792 B); sized 116KB
// to force 1 block/SM (128 blocks on 128 SMs, all co-resident -> barrier safe).
__global__ __launch_bounds__(256) void persist_lstm(
    const float* __restrict__ xpf, const float* __restrict__ xpb,
    const float* __restrict__ whhf, const float* __restrict__ whhb,
    float* __restrict__ out)
{
    extern __shared__ float sm[];
    float* wsm = sm;                 // [k][jl*4+g], stride 36
    float* hsm = sm + 512 * 36;      // [k][b], stride 132

    int bid = blockIdx.x;
    int dir = bid >> 6;
    int j0 = (bid & 63) * 8;
    const float* xp  = dir ? xpb : xpf;
    const float* whh = dir ? whhb : whhf;

    int tid = threadIdx.x;
    int jl = tid & 7, bg = tid >> 3;
    int b0v = bg * 4;
    int j = j0 + jl;

    // load Whh slice once: 4 gates x 8 j x 512 k
#pragma unroll 4
    for (int i = 0; i < 64; i++) {
        int idx = tid + i * 256;
        int g = idx >> 12;
        int jj = (idx >> 9) & 7;
        int k = idx & 511;
        wsm[k * 36 + jj * 4 + g] = whh[((size_t)(g * Hn + j0 + jj)) * Hn + k];
    }
    float c4[4] = {0.f, 0.f, 0.f, 0.f};
    __syncthreads();

    for (int s = 0; s < Sn; s++) {
        int t = dir ? (Sn - 1 - s) : s;
        const float* hin = d_hst[dir][s & 1];
        float* hout = d_hst[dir][(s & 1) ^ 1];

        unsigned long long acc[2][4];
#pragma unroll
        for (int p = 0; p < 2; p++)
#pragma unroll
            for (int g = 0; g < 4; g++) acc[p][g] = 0ull;

        for (int kt = 0; kt < Hn; kt += 64) {
#pragma unroll
            for (int i = 0; i < 8; i++) {
                int q = tid + i * 256;
                int b = q >> 4, kq = q & 15;
                float4 v = *(const float4*)(hin + (size_t)b * Hn + kt + kq * 4);
                hsm[(kq * 4 + 0) * 132 + b] = v.x;
                hsm[(kq * 4 + 1) * 132 + b] = v.y;
                hsm[(kq * 4 + 2) * 132 + b] = v.z;
                hsm[(kq * 4 + 3) * 132 + b] = v.w;
            }
            __syncthreads();
#pragma unroll 8
            for (int k = 0; k < 64; k++) {
                ulonglong2 hv = *(const ulonglong2*)&hsm[k * 132 + b0v];
                float4 wv = *(const float4*)&wsm[(kt + k) * 36 + jl * 4];
                unsigned long long w0 = pk2(wv.x, wv.x);
                unsigned long long w1 = pk2(wv.y, wv.y);
                unsigned long long w2 = pk2(wv.z, wv.z);
                unsigned long long w3 = pk2(wv.w, wv.w);
                acc[0][0] = ffma2(hv.x, w0, acc[0][0]);
                acc[0][1] = ffma2(hv.x, w1, acc[0][1]);
                acc[0][2] = ffma2(hv.x, w2, acc[0][2]);
                acc[0][3] = ffma2(hv.x, w3, acc[0][3]);
                acc[1][0] = ffma2(hv.y, w0, acc[1][0]);
                acc[1][1] = ffma2(hv.y, w1, acc[1][1]);
                acc[1][2] = ffma2(hv.y, w2, acc[1][2]);
                acc[1][3] = ffma2(hv.y, w3, acc[1][3]);
            }
            __syncthreads();
        }

        // gates + activations; xp layout [t][g*512+j][b]
        size_t xbase = (size_t)t * G4n * Bn;
        float ga[4][4];
#pragma unroll
        for (int g = 0; g < 4; g++) {
            float4 xv = *(const float4*)(xp + xbase + (size_t)(g * Hn + j) * Bn + b0v);
            float2 p0 = up2(acc[0][g]);
            float2 p1 = up2(acc[1][g]);
            ga[0][g] = p0.x + xv.x; ga[1][g] = p0.y + xv.y;
            ga[2][g] = p1.x + xv.z; ga[3][g] = p1.y + xv.w;
        }
#pragma unroll
        for (int bi = 0; bi < 4; bi++) {
            int b = b0v + bi;
            float ig = 1.f / (1.f + expf(-ga[bi][0]));
            float fg = 1.f / (1.f + expf(-ga[bi][1]));
            float og = 1.f / (1.f + expf(-ga[bi][3]));
            float cc = fg * c4[bi] + ig * tanhf(ga[bi][2]);
            float hh = og * tanhf(cc);
            c4[bi] = cc;
            hout[b * Hn + j] = hh;
            out[((size_t)t * Bn + b) * (2 * Hn) + dir * Hn + j] = hh;
        }

        // per-dir global barrier across the 64 blocks of this direction
        __syncthreads();
        if (tid == 0) {
            __threadfence();
            unsigned old = g_gen[dir];
            if (atomicAdd(&g_cnt[dir], 1u) == 63u) {
                g_cnt[dir] = 0;
                __threadfence();
                g_gen[dir] = old + 1u;
            } else {
                while (g_gen[dir] == old) { }
                __threadfence();
            }
        }
        __syncthreads();
    }
}

// ---------------- emissions: em[row][t] = hfc[row] . cls_w[t] + cls_b[t] ----------
__global__ void emissions_kernel(const float* __restrict__ hfc,
                                 const float* __restrict__ cls_w,
                                 const float* __restrict__ cls_b)
{
    int warp = blockIdx.x * 8 + (threadIdx.x >> 5);
    int lane = threadIdx.x & 31;
    const float* hrow = hfc + (size_t)warp * Hn;
    float hv[16];
#pragma unroll
    for (int q = 0; q < 16; q++) hv[q] = hrow[lane + q * 32];
    for (int tt = 0; tt < Tn; tt++) {
        const float* wr = cls_w + tt * Hn;
        float s = 0.f;
#pragma unroll
        for (int q = 0; q < 16; q++) s += hv[q] * wr[lane + q * 32];
#pragma unroll
        for (int o = 16; o > 0; o >>= 1) s += __shfl_xor_sync(0xffffffffu, s, o);
        if (lane == 0) d_em[(size_t)warp * Tn + tt] = s + cls_b[tt];
    }
}

// ---------------- CRF gold-path score (numerator) ----------------
__global__ void crf_num_kernel(const int* __restrict__ ids, const int* __restrict__ tags,
                               const float* __restrict__ trans,
                               const float* __restrict__ start_t, const float* __restrict__ end_t)
{
    int b = threadIdx.x;
    int tg0 = tags[b * Sn + 0];
    float score = start_t[tg0] + d_em[(size_t)b * Tn + tg0];
    int cnt = (ids[b * Sn + 0] != 0) ? 1 : 0;
    int prev = tg0;
    for (int s = 1; s < Sn; s++) {
        int tg = tags[b * Sn + s];
        if (ids[b * Sn + s] != 0) {
            score += trans[prev * Tn + tg] + d_em[((size_t)s * Bn + b) * Tn + tg];
            cnt++;
        }
        prev = tg;
    }
    int se = cnt - 1; if (se < 0) se = 0;
    d_num[b] = score + end_t[tags[b * Sn + se]];
}

// ---------------- CRF forward algorithm (denominator) ----------------
__global__ void crf_fwd_kernel(const int* __restrict__ ids,
                               const float* __restrict__ trans,
                               const float* __restrict__ start_t,
                               const float* __restrict__ end_t)
{
    int b = blockIdx.x;
    int j = threadIdx.x;
    __shared__ float alpha[Tn];
    __shared__ float tr[Tn * Tn];
    for (int idx = j; idx < Tn * Tn; idx += 32) tr[idx] = trans[idx];
    if (j < Tn) alpha[j] = start_t[j] + d_em[(size_t)b * Tn + j];
    __syncthreads();
    for (int s = 1; s < Sn; s++) {
        bool m = ids[b * Sn + s] != 0;
        float ns = 0.f;
        if (m && j < Tn) {
            float mx = -1e30f;
#pragma unroll
            for (int i = 0; i < Tn; i++) mx = fmaxf(mx, alpha[i] + tr[i * Tn + j]);
            float sum = 0.f;
#pragma unroll
            for (int i = 0; i < Tn; i++) sum += expf(alpha[i] + tr[i * Tn + j] - mx);
            ns = mx + logf(sum) + d_em[((size_t)s * Bn + b) * Tn + j];
        }
        __syncthreads();
        if (m && j < Tn) alpha[j] = ns;
        __syncthreads();
    }
    if (j == 0) {
        float mx = -1e30f;
        for (int i = 0; i < Tn; i++) mx = fmaxf(mx, alpha[i] + end_t[i]);
        float sum = 0.f;
        for (int i = 0; i < Tn; i++) sum += expf(alpha[i] + end_t[i] - mx);
        d_den[b] = mx + logf(sum);
    }
}

// ---------------- final: out = mean(num - den) ----------------
__global__ void final_kernel(float* __restrict__ out)
{
    int tid = threadIdx.x;
    __shared__ float sm[128];
    sm[tid] = d_num[tid] - d_den[tid];
    __syncthreads();
    for (int o = 64; o > 0; o >>= 1) {
        if (tid < o) sm[tid] += sm[tid + o];
        __syncthreads();
    }
    if (tid == 0) out[0] = sm[0] / 128.f;
}

// ---------------- launch ----------------
extern "C" void kernel_launch(void* const* d_in, const int* in_sizes, int n_in,
                              void* d_out, int out_size)
{
    (void)in_sizes; (void)n_in; (void)out_size;
    const int*   ids      = (const int*)d_in[0];
    const int*   tags     = (const int*)d_in[1];
    const float* emb      = (const float*)d_in[2];
    const float* w_ih_l0f = (const float*)d_in[3];
    const float* w_hh_l0f = (const float*)d_in[4];
    const float* b_l0f    = (const float*)d_in[5];
    const float* w_ih_l0b = (const float*)d_in[6];
    const float* w_hh_l0b = (const float*)d_in[7];
    const float* b_l0b    = (const float*)d_in[8];
    const float* w_ih_l1f = (const float*)d_in[9];
    const float* w_hh_l1f = (const float*)d_in[10];
    const float* b_l1f    = (const float*)d_in[11];
    const float* w_ih_l1b = (const float*)d_in[12];
    const float* w_hh_l1b = (const float*)d_in[13];
    const float* b_l1b    = (const float*)d_in[14];
    const float* fc_w     = (const float*)d_in[15];
    const float* fc_b     = (const float*)d_in[16];
    const float* cls_w    = (const float*)d_in[17];
    const float* cls_b    = (const float*)d_in[18];
    const float* trans    = (const float*)d_in[19];
    const float* start_t  = (const float*)d_in[20];
    const float* end_t    = (const float*)d_in[21];
    float* out = (float*)d_out;

    float *px, *pxf, *pxb, *pout0, *pout1, *phfc, *phst;
    cudaGetSymbolAddress((void**)&px,    d_x);
    cudaGetSymbolAddress((void**)&pxf,   d_xp_f);
    cudaGetSymbolAddress((void**)&pxb,   d_xp_b);
    cudaGetSymbolAddress((void**)&pout0, d_out0);
    cudaGetSymbolAddress((void**)&pout1, d_out1);
    cudaGetSymbolAddress((void**)&phfc,  d_hfc);
    cudaGetSymbolAddress((void**)&phst,  d_hst);

    const int SMEM_DYN = 118784;  // forces 1 block/SM (2x = 232KB > 228KB)
    cudaFuncSetAttribute(persist_lstm, cudaFuncAttributeMaxDynamicSharedMemorySize, SMEM_DYN);

    embed_kernel<<<Sn * Bn, 64>>>(ids, emb);

    // layer 0 input projections -> [t][g*512+j][b]
    dim3 g0(G4n / 128, Sn);
    sgemm_nt2<<<g0, 256>>>(px, w_ih_l0f, b_l0f, pxf, G4n, En, 0, 1);
    sgemm_nt2<<<g0, 256>>>(px, w_ih_l0b, b_l0b, pxb, G4n, En, 0, 1);

    cudaMemsetAsync(phst, 0, sizeof(d_hst), 0);
    persist_lstm<<<128, 256, SMEM_DYN>>>(pxf, pxb, w_hh_l0f, w_hh_l0b, pout0);

    // layer 1 input projections
    sgemm_nt2<<<g0, 256>>>(pout0, w_ih_l1f, b_l1f, pxf, G4n, 2 * Hn, 0, 1);
    sgemm_nt2<<<g0, 256>>>(pout0, w_ih_l1b, b_l1b, pxb, G4n, 2 * Hn, 0, 1);

    cudaMemsetAsync(phst, 0, sizeof(d_hst), 0);
    persist_lstm<<<128, 256, SMEM_DYN>>>(pxf, pxb, w_hh_l1f, w_hh_l1b, pout1);

    // fc + relu (row-major output)
    dim3 gfc(Hn / 128, Sn);
    sgemm_nt2<<<gfc, 256>>>(pout1, fc_w, fc_b, phfc, Hn, 2 * Hn, 1, 0);

    emissions_kernel<<<(Sn * Bn) / 8, 256>>>(phfc, cls_w, cls_b);
    crf_num_kernel<<<1, Bn>>>(ids, tags, trans, start_t, end_t);
    crf_fwd_kernel<<<Bn, 32>>>(ids, trans, start_t, end_t);
    final_kernel<<<1, Bn>>>(out);
}

// round 4
// speedup vs baseline: 2.2103x; 1.3446x over previous
#include <cuda_runtime.h>
#include <cuda_bf16.h>
#include <math.h>

#define Sn 256
#define Bn 128
#define En 256
#define Hn 512
#define Tn 18
#define G4n 2048

// ---------------- scratch (device globals; no cudaMalloc allowed) ----------------
__device__ __nv_bfloat16 d_xb[Sn * Bn * En];          // embedded input, bf16
__device__ float d_xp_f[Sn * Bn * G4n];               // input projection fwd [t][b][g*512+j]
__device__ float d_xp_b[Sn * Bn * G4n];               // input projection bwd
__device__ __nv_bfloat16 d_out0b[Sn * Bn * 2 * Hn];   // layer0 output bf16 [t][b][2H]
__device__ __nv_bfloat16 d_out1b[Sn * Bn * 2 * Hn];   // layer1 output bf16
__device__ float d_hfc[Sn * Bn * Hn];
__device__ float d_em[Sn * Bn * Tn];
__device__ float d_hst[2][2][Bn * Hn];                // h state [dir][parity][b*H+j]
__device__ float d_num[Bn];
__device__ float d_den[Bn];
__device__ unsigned g_cnt[2];
__device__ volatile unsigned g_gen[2];
// bf16 weight copies
__device__ __nv_bfloat16 d_wb_l0f[G4n * En];
__device__ __nv_bfloat16 d_wb_l0b[G4n * En];
__device__ __nv_bfloat16 d_wb_l1f[G4n * 2 * Hn];
__device__ __nv_bfloat16 d_wb_l1b[G4n * 2 * Hn];
__device__ __nv_bfloat16 d_wb_fc[Hn * 2 * Hn];

// ---------------- packed f32x2 helpers ----------------
__device__ __forceinline__ unsigned long long ffma2(unsigned long long a,
                                                    unsigned long long b,
                                                    unsigned long long c) {
    unsigned long long d;
    asm("fma.rn.f32x2 %0, %1, %2, %3;" : "=l"(d) : "l"(a), "l"(b), "l"(c));
    return d;
}
__device__ __forceinline__ unsigned long long pk2(float x, float y) {
    unsigned long long r;
    asm("mov.b64 %0, {%1, %2};" : "=l"(r) : "f"(x), "f"(y));
    return r;
}
__device__ __forceinline__ float2 up2(unsigned long long v) {
    float2 r;
    asm("mov.b64 {%0, %1}, %2;" : "=f"(r.x), "=f"(r.y) : "l"(v));
    return r;
}

// ---------------- fp32 -> bf16 convert ----------------
__global__ void f2bf_kernel(const float* __restrict__ src, __nv_bfloat16* __restrict__ dst, int n4)
{
    int i = blockIdx.x * blockDim.x + threadIdx.x;
    if (i >= n4) return;
    float4 v = ((const float4*)src)[i];
    __nv_bfloat162 h0 = __floats2bfloat162_rn(v.x, v.y);
    __nv_bfloat162 h1 = __floats2bfloat162_rn(v.z, v.w);
    ((__nv_bfloat162*)dst)[i * 2]     = h0;
    ((__nv_bfloat162*)dst)[i * 2 + 1] = h1;
}

// ---------------- embedding lookup (padding_idx=0 -> zeros), bf16 out ----------------
__global__ void embed_kernel(const int* __restrict__ ids, const float* __restrict__ emb)
{
    int n = blockIdx.x;          // n = s*B + b
    int s = n >> 7;
    int b = n & 127;
    int id = ids[b * Sn + s];
    float4 v;
    if (id == 0) v = make_float4(0.f, 0.f, 0.f, 0.f);
    else         v = ((const float4*)(emb + (size_t)id * En))[threadIdx.x];
    __nv_bfloat162 h0 = __floats2bfloat162_rn(v.x, v.y);
    __nv_bfloat162 h1 = __floats2bfloat162_rn(v.z, v.w);
    __nv_bfloat162* dst = (__nv_bfloat162*)(d_xb + (size_t)n * En);
    dst[threadIdx.x * 2]     = h0;
    dst[threadIdx.x * 2 + 1] = h1;
}

// ---------------- bf16 tensor-core GEMM (NT): C[M,N] = A[M,K] * W[N,K]^T + bias ---
// mma.sync.m16n8k16, fp32 accum. BM=128, BN=128, BK=32, 256 threads (8 warps 2x4),
// warp tile 64x32. K % 32 == 0, M % 128 == 0, N % 128 == 0.
__global__ __launch_bounds__(256) void gemm_bf16(
    const __nv_bfloat16* __restrict__ A, const __nv_bfloat16* __restrict__ W,
    const float* __restrict__ bias, float* __restrict__ C,
    int N, int K, int relu)
{
    __shared__ __nv_bfloat16 As[128 * 40];
    __shared__ __nv_bfloat16 Bs[128 * 40];

    int tid = threadIdx.x;
    int lane = tid & 31, wid = tid >> 5;
    int wm = wid >> 2, wn = wid & 3;
    int m0 = blockIdx.y << 7, n0 = blockIdx.x << 7;

    unsigned as_u32 = (unsigned)__cvta_generic_to_shared(As);
    unsigned bs_u32 = (unsigned)__cvta_generic_to_shared(Bs);
    // ldmatrix lane base addresses (bytes)
    unsigned a_base = as_u32 + ((wm * 64 + (lane & 15)) * 40 + ((lane >> 4) * 8)) * 2;
    unsigned b_base = bs_u32 + ((wn * 32 + (lane & 7)) * 40 + (((lane >> 3) & 1) * 8)) * 2;

    float acc[4][4][4];
#pragma unroll
    for (int i = 0; i < 4; i++)
#pragma unroll
        for (int j = 0; j < 4; j++)
#pragma unroll
            for (int r = 0; r < 4; r++) acc[i][j][r] = 0.f;

    for (int k0 = 0; k0 < K; k0 += 32) {
#pragma unroll
        for (int i = 0; i < 2; i++) {
            int q = tid * 2 + i;
            int r = q >> 2, c = (q & 3) * 8;
            *(uint4*)&As[r * 40 + c] = *(const uint4*)&A[(size_t)(m0 + r) * K + k0 + c];
            *(uint4*)&Bs[r * 40 + c] = *(const uint4*)&W[(size_t)(n0 + r) * K + k0 + c];
        }
        __syncthreads();
#pragma unroll
        for (int kk = 0; kk < 2; kk++) {
            unsigned af[4][4], bf[4][2];
#pragma unroll
            for (int i = 0; i < 4; i++) {
                unsigned addr = a_base + i * 1280 + kk * 32;
                asm volatile("ldmatrix.sync.aligned.m8n8.x4.shared.b16 {%0,%1,%2,%3}, [%4];"
                    : "=r"(af[i][0]), "=r"(af[i][1]), "=r"(af[i][2]), "=r"(af[i][3])
                    : "r"(addr));
            }
#pragma unroll
            for (int j = 0; j < 4; j++) {
                unsigned addr = b_base + j * 640 + kk * 32;
                asm volatile("ldmatrix.sync.aligned.m8n8.x2.shared.b16 {%0,%1}, [%2];"
                    : "=r"(bf[j][0]), "=r"(bf[j][1]) : "r"(addr));
            }
#pragma unroll
            for (int i = 0; i < 4; i++)
#pragma unroll
                for (int j = 0; j < 4; j++) {
                    asm volatile(
                        "mma.sync.aligned.m16n8k16.row.col.f32.bf16.bf16.f32 "
                        "{%0,%1,%2,%3}, {%4,%5,%6,%7}, {%8,%9}, {%0,%1,%2,%3};"
                        : "+f"(acc[i][j][0]), "+f"(acc[i][j][1]),
                          "+f"(acc[i][j][2]), "+f"(acc[i][j][3])
                        : "r"(af[i][0]), "r"(af[i][1]), "r"(af[i][2]), "r"(af[i][3]),
                          "r"(bf[j][0]), "r"(bf[j][1]));
                }
        }
        __syncthreads();
    }

#pragma unroll
    for (int i = 0; i < 4; i++) {
        int mb = m0 + wm * 64 + i * 16 + (lane >> 2);
#pragma unroll
        for (int j = 0; j < 4; j++) {
            int nb = n0 + wn * 32 + j * 8 + (lane & 3) * 2;
            float bx = bias[nb], by = bias[nb + 1];
            float2 v0 = make_float2(acc[i][j][0] + bx, acc[i][j][1] + by);
            float2 v1 = make_float2(acc[i][j][2] + bx, acc[i][j][3] + by);
            if (relu) {
                v0.x = fmaxf(v0.x, 0.f); v0.y = fmaxf(v0.y, 0.f);
                v1.x = fmaxf(v1.x, 0.f); v1.y = fmaxf(v1.y, 0.f);
            }
            *(float2*)&C[(size_t)mb * N + nb]       = v0;
            *(float2*)&C[(size_t)(mb + 8) * N + nb] = v1;
        }
    }
}

// ---------------- persistent BiLSTM layer kernel ----------------
// grid = 128 blocks (64 per dir), 256 threads. Block owns 8 h-columns (j-slice),
// Whh slice resident in smem, c in registers, per-dir global barrier each step.
__global__ __launch_bounds__(256) void persist_lstm(
    const float* __restrict__ xpf, const float* __restrict__ xpb,
    const float* __restrict__ whhf, const float* __restrict__ whhb,
    __nv_bfloat16* __restrict__ out)
{
    extern __shared__ float sm[];
    float* wsm = sm;                 // [k][jl*4+g], stride 36
    float* hsm = sm + 512 * 36;      // [k][b], stride 132

    int bid = blockIdx.x;
    int dir = bid >> 6;
    int j0 = (bid & 63) * 8;
    const float* xp  = dir ? xpb : xpf;
    const float* whh = dir ? whhb : whhf;

    int tid = threadIdx.x;
    int jl = tid & 7, bg = tid >> 3;
    int b0v = bg * 4;
    int j = j0 + jl;

#pragma unroll 4
    for (int i = 0; i < 64; i++) {
        int idx = tid + i * 256;
        int g = idx >> 12;
        int jj = (idx >> 9) & 7;
        int k = idx & 511;
        wsm[k * 36 + jj * 4 + g] = whh[((size_t)(g * Hn + j0 + jj)) * Hn + k];
    }
    float c4[4] = {0.f, 0.f, 0.f, 0.f};
    __syncthreads();

    for (int s = 0; s < Sn; s++) {
        int t = dir ? (Sn - 1 - s) : s;
        const float* hin = d_hst[dir][s & 1];
        float* hout = d_hst[dir][(s & 1) ^ 1];

        unsigned long long acc[2][4];
#pragma unroll
        for (int p = 0; p < 2; p++)
#pragma unroll
            for (int g = 0; g < 4; g++) acc[p][g] = 0ull;

        for (int kt = 0; kt < Hn; kt += 64) {
#pragma unroll
            for (int i = 0; i < 8; i++) {
                int q = tid + i * 256;
                int b = q >> 4, kq = q & 15;
                float4 v = *(const float4*)(hin + (size_t)b * Hn + kt + kq * 4);
                hsm[(kq * 4 + 0) * 132 + b] = v.x;
                hsm[(kq * 4 + 1) * 132 + b] = v.y;
                hsm[(kq * 4 + 2) * 132 + b] = v.z;
                hsm[(kq * 4 + 3) * 132 + b] = v.w;
            }
            __syncthreads();
#pragma unroll 8
            for (int k = 0; k < 64; k++) {
                ulonglong2 hv = *(const ulonglong2*)&hsm[k * 132 + b0v];
                float4 wv = *(const float4*)&wsm[(kt + k) * 36 + jl * 4];
                unsigned long long w0 = pk2(wv.x, wv.x);
                unsigned long long w1 = pk2(wv.y, wv.y);
                unsigned long long w2 = pk2(wv.z, wv.z);
                unsigned long long w3 = pk2(wv.w, wv.w);
                acc[0][0] = ffma2(hv.x, w0, acc[0][0]);
                acc[0][1] = ffma2(hv.x, w1, acc[0][1]);
                acc[0][2] = ffma2(hv.x, w2, acc[0][2]);
                acc[0][3] = ffma2(hv.x, w3, acc[0][3]);
                acc[1][0] = ffma2(hv.y, w0, acc[1][0]);
                acc[1][1] = ffma2(hv.y, w1, acc[1][1]);
                acc[1][2] = ffma2(hv.y, w2, acc[1][2]);
                acc[1][3] = ffma2(hv.y, w3, acc[1][3]);
            }
            __syncthreads();
        }

        // unpack accs -> gates; xp row-major [t][b][g*512+j]
        float ga[4][4];
#pragma unroll
        for (int g = 0; g < 4; g++) {
            float2 p0 = up2(acc[0][g]);
            float2 p1 = up2(acc[1][g]);
            ga[0][g] = p0.x; ga[1][g] = p0.y; ga[2][g] = p1.x; ga[3][g] = p1.y;
        }
#pragma unroll
        for (int bi = 0; bi < 4; bi++) {
            int b = b0v + bi;
            size_t xb = ((size_t)t * Bn + b) * G4n;
            float gi = ga[bi][0] + xp[xb + 0 * Hn + j];
            float gf = ga[bi][1] + xp[xb + 1 * Hn + j];
            float gg = ga[bi][2] + xp[xb + 2 * Hn + j];
            float go = ga[bi][3] + xp[xb + 3 * Hn + j];
            float ig = 1.f / (1.f + expf(-gi));
            float fg = 1.f / (1.f + expf(-gf));
            float og = 1.f / (1.f + expf(-go));
            float cc = fg * c4[bi] + ig * tanhf(gg);
            float hh = og * tanhf(cc);
            c4[bi] = cc;
            hout[b * Hn + j] = hh;
            out[((size_t)t * Bn + b) * (2 * Hn) + dir * Hn + j] = __float2bfloat16(hh);
        }

        // per-dir global barrier across the 64 blocks of this direction
        __syncthreads();
        if (tid == 0) {
            __threadfence();
            unsigned old = g_gen[dir];
            if (atomicAdd(&g_cnt[dir], 1u) == 63u) {
                g_cnt[dir] = 0;
                __threadfence();
                g_gen[dir] = old + 1u;
            } else {
                while (g_gen[dir] == old) { }
                __threadfence();
            }
        }
        __syncthreads();
    }
}

// ---------------- emissions: em[row][t] = hfc[row] . cls_w[t] + cls_b[t] ----------
__global__ void emissions_kernel(const float* __restrict__ hfc,
                                 const float* __restrict__ cls_w,
                                 const float* __restrict__ cls_b)
{
    int warp = blockIdx.x * 8 + (threadIdx.x >> 5);
    int lane = threadIdx.x & 31;
    const float* hrow = hfc + (size_t)warp * Hn;
    float hv[16];
#pragma unroll
    for (int q = 0; q < 16; q++) hv[q] = hrow[lane + q * 32];
    for (int tt = 0; tt < Tn; tt++) {
        const float* wr = cls_w + tt * Hn;
        float s = 0.f;
#pragma unroll
        for (int q = 0; q < 16; q++) s += hv[q] * wr[lane + q * 32];
#pragma unroll
        for (int o = 16; o > 0; o >>= 1) s += __shfl_xor_sync(0xffffffffu, s, o);
        if (lane == 0) d_em[(size_t)warp * Tn + tt] = s + cls_b[tt];
    }
}

// ---------------- CRF gold-path score (numerator) ----------------
__global__ void crf_num_kernel(const int* __restrict__ ids, const int* __restrict__ tags,
                               const float* __restrict__ trans,
                               const float* __restrict__ start_t, const float* __restrict__ end_t)
{
    int b = threadIdx.x;
    int tg0 = tags[b * Sn + 0];
    float score = start_t[tg0] + d_em[(size_t)b * Tn + tg0];
    int cnt = (ids[b * Sn + 0] != 0) ? 1 : 0;
    int prev = tg0;
    for (int s = 1; s < Sn; s++) {
        int tg = tags[b * Sn + s];
        if (ids[b * Sn + s] != 0) {
            score += trans[prev * Tn + tg] + d_em[((size_t)s * Bn + b) * Tn + tg];
            cnt++;
        }
        prev = tg;
    }
    int se = cnt - 1; if (se < 0) se = 0;
    d_num[b] = score + end_t[tags[b * Sn + se]];
}

// ---------------- CRF forward algorithm (denominator) ----------------
__global__ void crf_fwd_kernel(const int* __restrict__ ids,
                               const float* __restrict__ trans,
                               const float* __restrict__ start_t,
                               const float* __restrict__ end_t)
{
    int b = blockIdx.x;
    int j = threadIdx.x;
    __shared__ float alpha[Tn];
    __shared__ float tr[Tn * Tn];
    for (int idx = j; idx < Tn * Tn; idx += 32) tr[idx] = trans[idx];
    if (j < Tn) alpha[j] = start_t[j] + d_em[(size_t)b * Tn + j];
    __syncthreads();
    for (int s = 1; s < Sn; s++) {
        bool m = ids[b * Sn + s] != 0;
        float ns = 0.f;
        if (m && j < Tn) {
            float mx = -1e30f;
#pragma unroll
            for (int i = 0; i < Tn; i++) mx = fmaxf(mx, alpha[i] + tr[i * Tn + j]);
            float sum = 0.f;
#pragma unroll
            for (int i = 0; i < Tn; i++) sum += expf(alpha[i] + tr[i * Tn + j] - mx);
            ns = mx + logf(sum) + d_em[((size_t)s * Bn + b) * Tn + j];
        }
        __syncthreads();
        if (m && j < Tn) alpha[j] = ns;
        __syncthreads();
    }
    if (j == 0) {
        float mx = -1e30f;
        for (int i = 0; i < Tn; i++) mx = fmaxf(mx, alpha[i] + end_t[i]);
        float sum = 0.f;
        for (int i = 0; i < Tn; i++) sum += expf(alpha[i] + end_t[i] - mx);
        d_den[b] = mx + logf(sum);
    }
}

// ---------------- final: out = mean(num - den) ----------------
__global__ void final_kernel(float* __restrict__ out)
{
    int tid = threadIdx.x;
    __shared__ float sm[128];
    sm[tid] = d_num[tid] - d_den[tid];
    __syncthreads();
    for (int o = 64; o > 0; o >>= 1) {
        if (tid < o) sm[tid] += sm[tid + o];
        __syncthreads();
    }
    if (tid == 0) out[0] = sm[0] / 128.f;
}

// ---------------- launch ----------------
extern "C" void kernel_launch(void* const* d_in, const int* in_sizes, int n_in,
                              void* d_out, int out_size)
{
    (void)in_sizes; (void)n_in; (void)out_size;
    const int*   ids      = (const int*)d_in[0];
    const int*   tags     = (const int*)d_in[1];
    const float* emb      = (const float*)d_in[2];
    const float* w_ih_l0f = (const float*)d_in[3];
    const float* w_hh_l0f = (const float*)d_in[4];
    const float* b_l0f    = (const float*)d_in[5];
    const float* w_ih_l0b = (const float*)d_in[6];
    const float* w_hh_l0b = (const float*)d_in[7];
    const float* b_l0b    = (const float*)d_in[8];
    const float* w_ih_l1f = (const float*)d_in[9];
    const float* w_hh_l1f = (const float*)d_in[10];
    const float* b_l1f    = (const float*)d_in[11];
    const float* w_ih_l1b = (const float*)d_in[12];
    const float* w_hh_l1b = (const float*)d_in[13];
    const float* b_l1b    = (const float*)d_in[14];
    const float* fc_w     = (const float*)d_in[15];
    const float* fc_b     = (const float*)d_in[16];
    const float* cls_w    = (const float*)d_in[17];
    const float* cls_b    = (const float*)d_in[18];
    const float* trans    = (const float*)d_in[19];
    const float* start_t  = (const float*)d_in[20];
    const float* end_t    = (const float*)d_in[21];
    float* out = (float*)d_out;

    float *pxf, *pxb, *phfc, *phst;
    __nv_bfloat16 *pxbuf, *pout0b, *pout1b, *pw0f, *pw0b, *pw1f, *pw1b, *pwfc;
    cudaGetSymbolAddress((void**)&pxbuf, d_xb);
    cudaGetSymbolAddress((void**)&pxf,   d_xp_f);
    cudaGetSymbolAddress((void**)&pxb,   d_xp_b);
    cudaGetSymbolAddress((void**)&pout0b, d_out0b);
    cudaGetSymbolAddress((void**)&pout1b, d_out1b);
    cudaGetSymbolAddress((void**)&phfc,  d_hfc);
    cudaGetSymbolAddress((void**)&phst,  d_hst);
    cudaGetSymbolAddress((void**)&pw0f,  d_wb_l0f);
    cudaGetSymbolAddress((void**)&pw0b,  d_wb_l0b);
    cudaGetSymbolAddress((void**)&pw1f,  d_wb_l1f);
    cudaGetSymbolAddress((void**)&pw1b,  d_wb_l1b);
    cudaGetSymbolAddress((void**)&pwfc,  d_wb_fc);

    const int SMEM_DYN = 118784;  // forces 1 block/SM for persist_lstm
    cudaFuncSetAttribute(persist_lstm, cudaFuncAttributeMaxDynamicSharedMemorySize, SMEM_DYN);

    // weight converts (cheap, every replay for determinism)
    f2bf_kernel<<<(G4n * En / 4 + 255) / 256, 256>>>(w_ih_l0f, pw0f, G4n * En / 4);
    f2bf_kernel<<<(G4n * En / 4 + 255) / 256, 256>>>(w_ih_l0b, pw0b, G4n * En / 4);
    f2bf_kernel<<<(G4n * 2 * Hn / 4 + 255) / 256, 256>>>(w_ih_l1f, pw1f, G4n * 2 * Hn / 4);
    f2bf_kernel<<<(G4n * 2 * Hn / 4 + 255) / 256, 256>>>(w_ih_l1b, pw1b, G4n * 2 * Hn / 4);
    f2bf_kernel<<<(Hn * 2 * Hn / 4 + 255) / 256, 256>>>(fc_w, pwfc, Hn * 2 * Hn / 4);

    embed_kernel<<<Sn * Bn, 64>>>(ids, emb);

    // layer 0 input projections (row-major xp)
    dim3 g0(G4n / 128, (Sn * Bn) / 128);
    gemm_bf16<<<g0, 256>>>(pxbuf, pw0f, b_l0f, pxf, G4n, En, 0);
    gemm_bf16<<<g0, 256>>>(pxbuf, pw0b, b_l0b, pxb, G4n, En, 0);

    cudaMemsetAsync(phst, 0, sizeof(d_hst), 0);
    persist_lstm<<<128, 256, SMEM_DYN>>>(pxf, pxb, w_hh_l0f, w_hh_l0b, pout0b);

    // layer 1 input projections
    gemm_bf16<<<g0, 256>>>(pout0b, pw1f, b_l1f, pxf, G4n, 2 * Hn, 0);
    gemm_bf16<<<g0, 256>>>(pout0b, pw1b, b_l1b, pxb, G4n, 2 * Hn, 0);

    cudaMemsetAsync(phst, 0, sizeof(d_hst), 0);
    persist_lstm<<<128, 256, SMEM_DYN>>>(pxf, pxb, w_hh_l1f, w_hh_l1b, pout1b);

    // fc + relu
    dim3 gfc(Hn / 128, (Sn * Bn) / 128);
    gemm_bf16<<<gfc, 256>>>(pout1b, pwfc, fc_b, phfc, Hn, 2 * Hn, 1);

    emissions_kernel<<<(Sn * Bn) / 8, 256>>>(phfc, cls_w, cls_b);
    crf_num_kernel<<<1, Bn>>>(ids, tags, trans, start_t, end_t);
    crf_fwd_kernel<<<Bn, 32>>>(ids, trans, start_t, end_t);
    final_kernel<<<1, Bn>>>(out);
}

// round 6
// speedup vs baseline: 5.8308x; 2.6380x over previous
#include <cuda_runtime.h>
#include <cuda_bf16.h>
#include <math.h>

#define Sn 256
#define Bn 128
#define En 256
#define Hn 512
#define Tn 18
#define G4n 2048

// ---------------- scratch (device globals; no cudaMalloc allowed) ----------------
__device__ __nv_bfloat16 d_xb[Sn * Bn * En];          // embedded input, bf16
__device__ float d_xp_f[Sn * Bn * G4n];               // input projection fwd [t][b][g*512+j]
__device__ float d_xp_b[Sn * Bn * G4n];               // input projection bwd
__device__ __nv_bfloat16 d_out0b[Sn * Bn * 2 * Hn];   // layer0 output bf16 [t][b][2H]
__device__ __nv_bfloat16 d_out1b[Sn * Bn * 2 * Hn];   // layer1 output bf16
__device__ float d_hfc[Sn * Bn * Hn];
__device__ float d_em[Sn * Bn * Tn];
__device__ __nv_bfloat16 d_hstb[2][2][Bn * Hn];       // h state bf16 [dir][parity][b*H+j]
__device__ float d_num[Bn];
__device__ float d_den[Bn];
__device__ unsigned g_cnt[2];
__device__ volatile unsigned g_gen[2];
// bf16 weight copies (input projections + fc)
__device__ __nv_bfloat16 d_wb_l0f[G4n * En];
__device__ __nv_bfloat16 d_wb_l0b[G4n * En];
__device__ __nv_bfloat16 d_wb_l1f[G4n * 2 * Hn];
__device__ __nv_bfloat16 d_wb_l1b[G4n * 2 * Hn];
__device__ __nv_bfloat16 d_wb_fc[Hn * 2 * Hn];

// ---------------- fp32 -> bf16 convert ----------------
__global__ void f2bf_kernel(const float* __restrict__ src, __nv_bfloat16* __restrict__ dst, int n4)
{
    int i = blockIdx.x * blockDim.x + threadIdx.x;
    if (i >= n4) return;
    float4 v = ((const float4*)src)[i];
    __nv_bfloat162 h0 = __floats2bfloat162_rn(v.x, v.y);
    __nv_bfloat162 h1 = __floats2bfloat162_rn(v.z, v.w);
    ((__nv_bfloat162*)dst)[i * 2]     = h0;
    ((__nv_bfloat162*)dst)[i * 2 + 1] = h1;
}

// ---------------- embedding lookup (padding_idx=0 -> zeros), bf16 out ----------------
__global__ void embed_kernel(const int* __restrict__ ids, const float* __restrict__ emb)
{
    int n = blockIdx.x;          // n = s*B + b
    int s = n >> 7;
    int b = n & 127;
    int id = ids[b * Sn + s];
    float4 v;
    if (id == 0) v = make_float4(0.f, 0.f, 0.f, 0.f);
    else         v = ((const float4*)(emb + (size_t)id * En))[threadIdx.x];
    __nv_bfloat162 h0 = __floats2bfloat162_rn(v.x, v.y);
    __nv_bfloat162 h1 = __floats2bfloat162_rn(v.z, v.w);
    __nv_bfloat162* dst = (__nv_bfloat162*)(d_xb + (size_t)n * En);
    dst[threadIdx.x * 2]     = h0;
    dst[threadIdx.x * 2 + 1] = h1;
}

// ---------------- bf16 tensor-core GEMM (NT): C[M,N] = A[M,K] * W[N,K]^T + bias ---
__global__ __launch_bounds__(256) void gemm_bf16(
    const __nv_bfloat16* __restrict__ A, const __nv_bfloat16* __restrict__ W,
    const float* __restrict__ bias, float* __restrict__ C,
    int N, int K, int relu)
{
    __shared__ __nv_bfloat16 As[128 * 40];
    __shared__ __nv_bfloat16 Bs[128 * 40];

    int tid = threadIdx.x;
    int lane = tid & 31, wid = tid >> 5;
    int wm = wid >> 2, wn = wid & 3;
    int m0 = blockIdx.y << 7, n0 = blockIdx.x << 7;

    unsigned as_u32 = (unsigned)__cvta_generic_to_shared(As);
    unsigned bs_u32 = (unsigned)__cvta_generic_to_shared(Bs);
    unsigned a_base = as_u32 + ((wm * 64 + (lane & 15)) * 40 + ((lane >> 4) * 8)) * 2;
    unsigned b_base = bs_u32 + ((wn * 32 + (lane & 7)) * 40 + (((lane >> 3) & 1) * 8)) * 2;

    float acc[4][4][4];
#pragma unroll
    for (int i = 0; i < 4; i++)
#pragma unroll
        for (int j = 0; j < 4; j++)
#pragma unroll
            for (int r = 0; r < 4; r++) acc[i][j][r] = 0.f;

    for (int k0 = 0; k0 < K; k0 += 32) {
#pragma unroll
        for (int i = 0; i < 2; i++) {
            int q = tid * 2 + i;
            int r = q >> 2, c = (q & 3) * 8;
            *(uint4*)&As[r * 40 + c] = *(const uint4*)&A[(size_t)(m0 + r) * K + k0 + c];
            *(uint4*)&Bs[r * 40 + c] = *(const uint4*)&W[(size_t)(n0 + r) * K + k0 + c];
        }
        __syncthreads();
#pragma unroll
        for (int kk = 0; kk < 2; kk++) {
            unsigned af[4][4], bf[4][2];
#pragma unroll
            for (int i = 0; i < 4; i++) {
                unsigned addr = a_base + i * 1280 + kk * 32;
                asm volatile("ldmatrix.sync.aligned.m8n8.x4.shared.b16 {%0,%1,%2,%3}, [%4];"
                    : "=r"(af[i][0]), "=r"(af[i][1]), "=r"(af[i][2]), "=r"(af[i][3])
                    : "r"(addr));
            }
#pragma unroll
            for (int j = 0; j < 4; j++) {
                unsigned addr = b_base + j * 640 + kk * 32;
                asm volatile("ldmatrix.sync.aligned.m8n8.x2.shared.b16 {%0,%1}, [%2];"
                    : "=r"(bf[j][0]), "=r"(bf[j][1]) : "r"(addr));
            }
#pragma unroll
            for (int i = 0; i < 4; i++)
#pragma unroll
                for (int j = 0; j < 4; j++) {
                    asm volatile(
                        "mma.sync.aligned.m16n8k16.row.col.f32.bf16.bf16.f32 "
                        "{%0,%1,%2,%3}, {%4,%5,%6,%7}, {%8,%9}, {%0,%1,%2,%3};"
                        : "+f"(acc[i][j][0]), "+f"(acc[i][j][1]),
                          "+f"(acc[i][j][2]), "+f"(acc[i][j][3])
                        : "r"(af[i][0]), "r"(af[i][1]), "r"(af[i][2]), "r"(af[i][3]),
                          "r"(bf[j][0]), "r"(bf[j][1]));
                }
        }
        __syncthreads();
    }

#pragma unroll
    for (int i = 0; i < 4; i++) {
        int mb = m0 + wm * 64 + i * 16 + (lane >> 2);
#pragma unroll
        for (int j = 0; j < 4; j++) {
            int nb = n0 + wn * 32 + j * 8 + (lane & 3) * 2;
            float bx = bias[nb], by = bias[nb + 1];
            float2 v0 = make_float2(acc[i][j][0] + bx, acc[i][j][1] + by);
            float2 v1 = make_float2(acc[i][j][2] + bx, acc[i][j][3] + by);
            if (relu) {
                v0.x = fmaxf(v0.x, 0.f); v0.y = fmaxf(v0.y, 0.f);
                v1.x = fmaxf(v1.x, 0.f); v1.y = fmaxf(v1.y, 0.f);
            }
            *(float2*)&C[(size_t)mb * N + nb]       = v0;
            *(float2*)&C[(size_t)(mb + 8) * N + nb] = v1;
        }
    }
}

// ---------------- persistent BiLSTM layer, tensor-core recurrence ----------------
// grid = 128 blocks (64 per dir), 256 threads (8 warps, 4x2 warp grid).
// Block owns 8 j-columns x 4 gates = 32 output cols. Per step:
//   mma: M=128(b) x N=32(jl*4+g) x K=512(h), A = h bf16 (smem), B = Whh slice bf16 (smem).
// Gates go through a smem f32 buffer (overlaid on h tile) for the epilogue.
// h state bf16 in global, double-buffered by step parity; per-dir spin barrier.
__global__ __launch_bounds__(256) void persist_lstm_tc(
    const float* __restrict__ xpf, const float* __restrict__ xpb,
    const float* __restrict__ whhf, const float* __restrict__ whhb,
    __nv_bfloat16* __restrict__ out)
{
    extern __shared__ __nv_bfloat16 smb[];
    __nv_bfloat16* hs = smb;                    // [128][520] bf16 (133120 B)
    __nv_bfloat16* ws = smb + 128 * 520;        // [32][520]  bf16 (33280 B)
    float* gsm = (float*)smb;                   // overlay: [32][132] f32 (16896 B)

    int bid = blockIdx.x;
    int dir = bid >> 6;
    int j0 = (bid & 63) * 8;
    const float* xp  = dir ? xpb : xpf;
    const float* whh = dir ? whhb : whhf;

    int tid = threadIdx.x;
    int lane = tid & 31, wid = tid >> 5;
    int wm = wid >> 1, wn = wid & 1;            // 4x2 warp grid
    int jl = tid & 7, bg = tid >> 3;
    int b0v = bg * 4;
    int j = j0 + jl;

    // load Whh slice -> bf16 smem: row n = jl*4+g  <->  whh row (g*512 + j0 + jl)
#pragma unroll 4
    for (int it = 0; it < 64; it++) {
        int idx = it * 256 + tid;
        int n = idx >> 9, k = idx & 511;
        int grow = (n & 3) * Hn + j0 + (n >> 2);
        ws[n * 520 + k] = __float2bfloat16(whh[(size_t)grow * Hn + k]);
    }
    float c4[4] = {0.f, 0.f, 0.f, 0.f};
    __syncthreads();

    unsigned hs_u = (unsigned)__cvta_generic_to_shared(hs);
    unsigned ws_u = (unsigned)__cvta_generic_to_shared(ws);
    unsigned a_base = hs_u + ((wm * 32 + (lane & 15)) * 520 + (lane >> 4) * 8) * 2;
    unsigned b_base = ws_u + ((wn * 16 + (lane & 7)) * 520 + ((lane >> 3) & 1) * 8) * 2;

    for (int s = 0; s < Sn; s++) {
        int t = dir ? (Sn - 1 - s) : s;
        const __nv_bfloat16* hin = d_hstb[dir][s & 1];
        __nv_bfloat16* hout = d_hstb[dir][(s & 1) ^ 1];

        // prefetch xp gate pre-activations for this thread's (b, j) set
        float xr[4][4];
#pragma unroll
        for (int bi = 0; bi < 4; bi++) {
            size_t xb = ((size_t)t * Bn + b0v + bi) * G4n;
#pragma unroll
            for (int g = 0; g < 4; g++)
                xr[bi][g] = xp[xb + g * Hn + j];
        }

        // load h (128 x 512 bf16) -> smem
#pragma unroll 8
        for (int it = 0; it < 32; it++) {
            int idx = it * 256 + tid;
            int b = idx >> 6, c = (idx & 63) * 8;
            *(uint4*)&hs[b * 520 + c] = *(const uint4*)&hin[(size_t)b * Hn + c];
        }
        __syncthreads();

        // mma: per warp 2 m-tiles x 2 n-tiles x 32 k-steps
        float acc[2][2][4];
#pragma unroll
        for (int i = 0; i < 2; i++)
#pragma unroll
            for (int jt = 0; jt < 2; jt++)
#pragma unroll
                for (int r = 0; r < 4; r++) acc[i][jt][r] = 0.f;

#pragma unroll 4
        for (int k = 0; k < 32; k++) {
            unsigned af[2][4], bfr[2][2];
#pragma unroll
            for (int i = 0; i < 2; i++) {
                unsigned addr = a_base + i * (16 * 520 * 2) + k * 32;
                asm volatile("ldmatrix.sync.aligned.m8n8.x4.shared.b16 {%0,%1,%2,%3}, [%4];"
                    : "=r"(af[i][0]), "=r"(af[i][1]), "=r"(af[i][2]), "=r"(af[i][3])
                    : "r"(addr));
            }
#pragma unroll
            for (int jt = 0; jt < 2; jt++) {
                unsigned addr = b_base + jt * (8 * 520 * 2) + k * 32;
                asm volatile("ldmatrix.sync.aligned.m8n8.x2.shared.b16 {%0,%1}, [%2];"
                    : "=r"(bfr[jt][0]), "=r"(bfr[jt][1]) : "r"(addr));
            }
#pragma unroll
            for (int i = 0; i < 2; i++)
#pragma unroll
                for (int jt = 0; jt < 2; jt++) {
                    asm volatile(
                        "mma.sync.aligned.m16n8k16.row.col.f32.bf16.bf16.f32 "
                        "{%0,%1,%2,%3}, {%4,%5,%6,%7}, {%8,%9}, {%0,%1,%2,%3};"
                        : "+f"(acc[i][jt][0]), "+f"(acc[i][jt][1]),
                          "+f"(acc[i][jt][2]), "+f"(acc[i][jt][3])
                        : "r"(af[i][0]), "r"(af[i][1]), "r"(af[i][2]), "r"(af[i][3]),
                          "r"(bfr[jt][0]), "r"(bfr[jt][1]));
                }
        }
        __syncthreads();   // all warps done reading hs before gsm overlay

        // fragments -> gsm[n][b]
#pragma unroll
        for (int i = 0; i < 2; i++) {
            int m = wm * 32 + i * 16 + (lane >> 2);
#pragma unroll
            for (int jt = 0; jt < 2; jt++) {
                int n = wn * 16 + jt * 8 + (lane & 3) * 2;
                gsm[n * 132 + m]           = acc[i][jt][0];
                gsm[(n + 1) * 132 + m]     = acc[i][jt][1];
                gsm[n * 132 + m + 8]       = acc[i][jt][2];
                gsm[(n + 1) * 132 + m + 8] = acc[i][jt][3];
            }
        }
        __syncthreads();

        // epilogue: gates, activations, h/out stores
#pragma unroll
        for (int bi = 0; bi < 4; bi++) {
            int b = b0v + bi;
            float gi = gsm[(jl * 4 + 0) * 132 + b] + xr[bi][0];
            float gf = gsm[(jl * 4 + 1) * 132 + b] + xr[bi][1];
            float gg = gsm[(jl * 4 + 2) * 132 + b] + xr[bi][2];
            float go = gsm[(jl * 4 + 3) * 132 + b] + xr[bi][3];
            float ig = 1.f / (1.f + expf(-gi));
            float fg = 1.f / (1.f + expf(-gf));
            float og = 1.f / (1.f + expf(-go));
            float cc = fg * c4[bi] + ig * tanhf(gg);
            float hh = og * tanhf(cc);
            c4[bi] = cc;
            __nv_bfloat16 hb = __float2bfloat16(hh);
            hout[b * Hn + j] = hb;
            out[((size_t)t * Bn + b) * (2 * Hn) + dir * Hn + j] = hb;
        }

        // per-dir global barrier across the 64 blocks of this direction
        __syncthreads();
        if (tid == 0) {
            __threadfence();
            unsigned old = g_gen[dir];
            if (atomicAdd(&g_cnt[dir], 1u) == 63u) {
                g_cnt[dir] = 0;
                __threadfence();
                g_gen[dir] = old + 1u;
            } else {
                while (g_gen[dir] == old) { }
                __threadfence();
            }
        }
        __syncthreads();
    }
}

// ---------------- emissions: em[row][t] = hfc[row] . cls_w[t] + cls_b[t] ----------
__global__ void emissions_kernel(const float* __restrict__ hfc,
                                 const float* __restrict__ cls_w,
                                 const float* __restrict__ cls_b)
{
    int warp = blockIdx.x * 8 + (threadIdx.x >> 5);
    int lane = threadIdx.x & 31;
    const float* hrow = hfc + (size_t)warp * Hn;
    float hv[16];
#pragma unroll
    for (int q = 0; q < 16; q++) hv[q] = hrow[lane + q * 32];
    for (int tt = 0; tt < Tn; tt++) {
        const float* wr = cls_w + tt * Hn;
        float s = 0.f;
#pragma unroll
        for (int q = 0; q < 16; q++) s += hv[q] * wr[lane + q * 32];
#pragma unroll
        for (int o = 16; o > 0; o >>= 1) s += __shfl_xor_sync(0xffffffffu, s, o);
        if (lane == 0) d_em[(size_t)warp * Tn + tt] = s + cls_b[tt];
    }
}

// ---------------- CRF gold-path score (numerator) ----------------
__global__ void crf_num_kernel(const int* __restrict__ ids, const int* __restrict__ tags,
                               const float* __restrict__ trans,
                               const float* __restrict__ start_t, const float* __restrict__ end_t)
{
    int b = threadIdx.x;
    int tg0 = tags[b * Sn + 0];
    float score = start_t[tg0] + d_em[(size_t)b * Tn + tg0];
    int cnt = (ids[b * Sn + 0] != 0) ? 1 : 0;
    int prev = tg0;
    for (int s = 1; s < Sn; s++) {
        int tg = tags[b * Sn + s];
        if (ids[b * Sn + s] != 0) {
            score += trans[prev * Tn + tg] + d_em[((size_t)s * Bn + b) * Tn + tg];
            cnt++;
        }
        prev = tg;
    }
    int se = cnt - 1; if (se < 0) se = 0;
    d_num[b] = score + end_t[tags[b * Sn + se]];
}

// ---------------- CRF forward algorithm (denominator) ----------------
__global__ void crf_fwd_kernel(const int* __restrict__ ids,
                               const float* __restrict__ trans,
                               const float* __restrict__ start_t,
                               const float* __restrict__ end_t)
{
    int b = blockIdx.x;
    int j = threadIdx.x;
    __shared__ float alpha[Tn];
    __shared__ float tr[Tn * Tn];
    for (int idx = j; idx < Tn * Tn; idx += 32) tr[idx] = trans[idx];
    if (j < Tn) alpha[j] = start_t[j] + d_em[(size_t)b * Tn + j];
    __syncthreads();
    for (int s = 1; s < Sn; s++) {
        bool m = ids[b * Sn + s] != 0;
        float ns = 0.f;
        if (m && j < Tn) {
            float mx = -1e30f;
#pragma unroll
            for (int i = 0; i < Tn; i++) mx = fmaxf(mx, alpha[i] + tr[i * Tn + j]);
            float sum = 0.f;
#pragma unroll
            for (int i = 0; i < Tn; i++) sum += expf(alpha[i] + tr[i * Tn + j] - mx);
            ns = mx + logf(sum) + d_em[((size_t)s * Bn + b) * Tn + j];
        }
        __syncthreads();
        if (m && j < Tn) alpha[j] = ns;
        __syncthreads();
    }
    if (j == 0) {
        float mx = -1e30f;
        for (int i = 0; i < Tn; i++) mx = fmaxf(mx, alpha[i] + end_t[i]);
        float sum = 0.f;
        for (int i = 0; i < Tn; i++) sum += expf(alpha[i] + end_t[i] - mx);
        d_den[b] = mx + logf(sum);
    }
}

// ---------------- final: out = mean(num - den) ----------------
__global__ void final_kernel(float* __restrict__ out)
{
    int tid = threadIdx.x;
    __shared__ float sm[128];
    sm[tid] = d_num[tid] - d_den[tid];
    __syncthreads();
    for (int o = 64; o > 0; o >>= 1) {
        if (tid < o) sm[tid] += sm[tid + o];
        __syncthreads();
    }
    if (tid == 0) out[0] = sm[0] / 128.f;
}

// ---------------- launch ----------------
extern "C" void kernel_launch(void* const* d_in, const int* in_sizes, int n_in,
                              void* d_out, int out_size)
{
    (void)in_sizes; (void)n_in; (void)out_size;
    const int*   ids      = (const int*)d_in[0];
    const int*   tags     = (const int*)d_in[1];
    const float* emb      = (const float*)d_in[2];
    const float* w_ih_l0f = (const float*)d_in[3];
    const float* w_hh_l0f = (const float*)d_in[4];
    const float* b_l0f    = (const float*)d_in[5];
    const float* w_ih_l0b = (const float*)d_in[6];
    const float* w_hh_l0b = (const float*)d_in[7];
    const float* b_l0b    = (const float*)d_in[8];
    const float* w_ih_l1f = (const float*)d_in[9];
    const float* w_hh_l1f = (const float*)d_in[10];
    const float* b_l1f    = (const float*)d_in[11];
    const float* w_ih_l1b = (const float*)d_in[12];
    const float* w_hh_l1b = (const float*)d_in[13];
    const float* b_l1b    = (const float*)d_in[14];
    const float* fc_w     = (const float*)d_in[15];
    const float* fc_b     = (const float*)d_in[16];
    const float* cls_w    = (const float*)d_in[17];
    const float* cls_b    = (const float*)d_in[18];
    const float* trans    = (const float*)d_in[19];
    const float* start_t  = (const float*)d_in[20];
    const float* end_t    = (const float*)d_in[21];
    float* out = (float*)d_out;

    float *pxf, *pxb, *phfc;
    __nv_bfloat16 *pxbuf, *pout0b, *pout1b, *pw0f, *pw0b, *pw1f, *pw1b, *pwfc, *phstb;
    cudaGetSymbolAddress((void**)&pxbuf, d_xb);
    cudaGetSymbolAddress((void**)&pxf,   d_xp_f);
    cudaGetSymbolAddress((void**)&pxb,   d_xp_b);
    cudaGetSymbolAddress((void**)&pout0b, d_out0b);
    cudaGetSymbolAddress((void**)&pout1b, d_out1b);
    cudaGetSymbolAddress((void**)&phfc,  d_hfc);
    cudaGetSymbolAddress((void**)&phstb, d_hstb);
    cudaGetSymbolAddress((void**)&pw0f,  d_wb_l0f);
    cudaGetSymbolAddress((void**)&pw0b,  d_wb_l0b);
    cudaGetSymbolAddress((void**)&pw1f,  d_wb_l1f);
    cudaGetSymbolAddress((void**)&pw1b,  d_wb_l1b);
    cudaGetSymbolAddress((void**)&pwfc,  d_wb_fc);

    const int SMEM_LSTM = 128 * 520 * 2 + 32 * 520 * 2;  // 166400 B
    cudaFuncSetAttribute(persist_lstm_tc, cudaFuncAttributeMaxDynamicSharedMemorySize, SMEM_LSTM);

    // weight converts for the big GEMMs
    f2bf_kernel<<<(G4n * En / 4 + 255) / 256, 256>>>(w_ih_l0f, pw0f, G4n * En / 4);
    f2bf_kernel<<<(G4n * En / 4 + 255) / 256, 256>>>(w_ih_l0b, pw0b, G4n * En / 4);
    f2bf_kernel<<<(G4n * 2 * Hn / 4 + 255) / 256, 256>>>(w_ih_l1f, pw1f, G4n * 2 * Hn / 4);
    f2bf_kernel<<<(G4n * 2 * Hn / 4 + 255) / 256, 256>>>(w_ih_l1b, pw1b, G4n * 2 * Hn / 4);
    f2bf_kernel<<<(Hn * 2 * Hn / 4 + 255) / 256, 256>>>(fc_w, pwfc, Hn * 2 * Hn / 4);

    embed_kernel<<<Sn * Bn, 64>>>(ids, emb);

    // layer 0 input projections (row-major xp [t][b][g*512+j])
    dim3 g0(G4n / 128, (Sn * Bn) / 128);
    gemm_bf16<<<g0, 256>>>(pxbuf, pw0f, b_l0f, pxf, G4n, En, 0);
    gemm_bf16<<<g0, 256>>>(pxbuf, pw0b, b_l0b, pxb, G4n, En, 0);

    cudaMemsetAsync(phstb, 0, sizeof(d_hstb), 0);
    persist_lstm_tc<<<128, 256, SMEM_LSTM>>>(pxf, pxb, w_hh_l0f, w_hh_l0b, pout0b);

    // layer 1 input projections
    gemm_bf16<<<g0, 256>>>(pout0b, pw1f, b_l1f, pxf, G4n, 2 * Hn, 0);
    gemm_bf16<<<g0, 256>>>(pout0b, pw1b, b_l1b, pxb, G4n, 2 * Hn, 0);

    cudaMemsetAsync(phstb, 0, sizeof(d_hstb), 0);
    persist_lstm_tc<<<128, 256, SMEM_LSTM>>>(pxf, pxb, w_hh_l1f, w_hh_l1b, pout1b);

    // fc + relu
    dim3 gfc(Hn / 128, (Sn * Bn) / 128);
    gemm_bf16<<<gfc, 256>>>(pout1b, pwfc, fc_b, phfc, Hn, 2 * Hn, 1);

    emissions_kernel<<<(Sn * Bn) / 8, 256>>>(phfc, cls_w, cls_b);
    crf_num_kernel<<<1, Bn>>>(ids, tags, trans, start_t, end_t);
    crf_fwd_kernel<<<Bn, 32>>>(ids, trans, start_t, end_t);
    final_kernel<<<1, Bn>>>(out);
}

// round 8
// speedup vs baseline: 6.9722x; 1.1957x over previous
#include <cuda_runtime.h>
#include <cuda_bf16.h>
#include <math.h>

#define Sn 256
#define Bn 128
#define En 256
#define Hn 512
#define Tn 18
#define G4n 2048

// ---------------- scratch (device globals; no cudaMalloc allowed) ----------------
__device__ __nv_bfloat16 d_xb[Sn * Bn * En];          // embedded input, bf16
__device__ float d_xp_f[Sn * Bn * G4n];               // input projection fwd [t][b][g*512+j]
__device__ float d_xp_b[Sn * Bn * G4n];               // input projection bwd
__device__ __nv_bfloat16 d_out0b[Sn * Bn * 2 * Hn];   // layer0 output bf16 [t][b][2H]
__device__ __nv_bfloat16 d_out1b[Sn * Bn * 2 * Hn];   // layer1 output bf16
__device__ float d_hfc[Sn * Bn * Hn];
__device__ float d_em[Sn * Bn * Tn];
__device__ __nv_bfloat16 d_hstb[2][2][Bn * Hn];       // h state bf16 [dir][parity][b*H+j]
__device__ float d_num[Bn];
__device__ float d_den[Bn];
__device__ unsigned g_cnt[2];
__device__ volatile unsigned g_gen[2];
// bf16 weight copies (input projections + fc)
__device__ __nv_bfloat16 d_wb_l0f[G4n * En];
__device__ __nv_bfloat16 d_wb_l0b[G4n * En];
__device__ __nv_bfloat16 d_wb_l1f[G4n * 2 * Hn];
__device__ __nv_bfloat16 d_wb_l1b[G4n * 2 * Hn];
__device__ __nv_bfloat16 d_wb_fc[Hn * 2 * Hn];

template<int N> __device__ __forceinline__ void cpwait() {
    asm volatile("cp.async.wait_group %0;" :: "n"(N));
}
__device__ __forceinline__ void cpcommit() {
    asm volatile("cp.async.commit_group;");
}
__device__ __forceinline__ void cpasync16(unsigned dst, const void* src) {
    asm volatile("cp.async.cg.shared.global [%0], [%1], 16;" :: "r"(dst), "l"(src));
}

// ---------------- fp32 -> bf16 convert ----------------
__global__ void f2bf_kernel(const float* __restrict__ src, __nv_bfloat16* __restrict__ dst, int n4)
{
    int i = blockIdx.x * blockDim.x + threadIdx.x;
    if (i >= n4) return;
    float4 v = ((const float4*)src)[i];
    __nv_bfloat162 h0 = __floats2bfloat162_rn(v.x, v.y);
    __nv_bfloat162 h1 = __floats2bfloat162_rn(v.z, v.w);
    ((__nv_bfloat162*)dst)[i * 2]     = h0;
    ((__nv_bfloat162*)dst)[i * 2 + 1] = h1;
}

// ---------------- embedding lookup (padding_idx=0 -> zeros), bf16 out ----------------
__global__ void embed_kernel(const int* __restrict__ ids, const float* __restrict__ emb)
{
    int n = blockIdx.x;          // n = s*B + b
    int s = n >> 7;
    int b = n & 127;
    int id = ids[b * Sn + s];
    float4 v;
    if (id == 0) v = make_float4(0.f, 0.f, 0.f, 0.f);
    else         v = ((const float4*)(emb + (size_t)id * En))[threadIdx.x];
    __nv_bfloat162 h0 = __floats2bfloat162_rn(v.x, v.y);
    __nv_bfloat162 h1 = __floats2bfloat162_rn(v.z, v.w);
    __nv_bfloat162* dst = (__nv_bfloat162*)(d_xb + (size_t)n * En);
    dst[threadIdx.x * 2]     = h0;
    dst[threadIdx.x * 2 + 1] = h1;
}

// ---------------- bf16 TC GEMM (NT), 2-stage cp.async pipeline -------------------
// C[M,N] = A[M,K] * W[N,K]^T + bias. BM=128, BN=128, BK=32, 256 thr (8 warps 2x4).
__global__ __launch_bounds__(256) void gemm_bf16(
    const __nv_bfloat16* __restrict__ A, const __nv_bfloat16* __restrict__ W,
    const float* __restrict__ bias, float* __restrict__ C,
    int N, int K, int relu)
{
    __shared__ __nv_bfloat16 As[2][128 * 40];
    __shared__ __nv_bfloat16 Bs[2][128 * 40];

    int tid = threadIdx.x;
    int lane = tid & 31, wid = tid >> 5;
    int wm = wid >> 2, wn = wid & 3;
    int m0 = blockIdx.y << 7, n0 = blockIdx.x << 7;

    unsigned as_u32 = (unsigned)__cvta_generic_to_shared(&As[0][0]);
    unsigned bs_u32 = (unsigned)__cvta_generic_to_shared(&Bs[0][0]);
    unsigned a_base = as_u32 + ((wm * 64 + (lane & 15)) * 40 + ((lane >> 4) * 8)) * 2;
    unsigned b_base = bs_u32 + ((wn * 32 + (lane & 7)) * 40 + (((lane >> 3) & 1) * 8)) * 2;
    const unsigned STB = 128 * 40 * 2;   // stage stride bytes

    // per-thread load coords (2 x 16B for A, 2 for B per stage)
    int r0 = (tid * 2) >> 2,     c0 = ((tid * 2) & 3) * 8;
    int r1 = (tid * 2 + 1) >> 2, c1 = ((tid * 2 + 1) & 3) * 8;

    float acc[4][4][4];
#pragma unroll
    for (int i = 0; i < 4; i++)
#pragma unroll
        for (int j = 0; j < 4; j++)
#pragma unroll
            for (int r = 0; r < 4; r++) acc[i][j][r] = 0.f;

    // prologue: stage 0
    cpasync16(as_u32 + (r0 * 40 + c0) * 2, &A[(size_t)(m0 + r0) * K + c0]);
    cpasync16(as_u32 + (r1 * 40 + c1) * 2, &A[(size_t)(m0 + r1) * K + c1]);
    cpasync16(bs_u32 + (r0 * 40 + c0) * 2, &W[(size_t)(n0 + r0) * K + c0]);
    cpasync16(bs_u32 + (r1 * 40 + c1) * 2, &W[(size_t)(n0 + r1) * K + c1]);
    cpcommit();

    int st = 0;
    for (int k0 = 0; k0 < K; k0 += 32) {
        bool more = (k0 + 32) < K;
        if (more) {
            unsigned so = (st ^ 1) * STB;
            cpasync16(as_u32 + so + (r0 * 40 + c0) * 2, &A[(size_t)(m0 + r0) * K + k0 + 32 + c0]);
            cpasync16(as_u32 + so + (r1 * 40 + c1) * 2, &A[(size_t)(m0 + r1) * K + k0 + 32 + c1]);
            cpasync16(bs_u32 + so + (r0 * 40 + c0) * 2, &W[(size_t)(n0 + r0) * K + k0 + 32 + c0]);
            cpasync16(bs_u32 + so + (r1 * 40 + c1) * 2, &W[(size_t)(n0 + r1) * K + k0 + 32 + c1]);
            cpcommit();
            cpwait<1>();
        } else {
            cpwait<0>();
        }
        __syncthreads();

        unsigned so = st * STB;
#pragma unroll
        for (int kk = 0; kk < 2; kk++) {
            unsigned af[4][4], bf[4][2];
#pragma unroll
            for (int i = 0; i < 4; i++) {
                unsigned addr = a_base + so + i * 1280 + kk * 32;
                asm volatile("ldmatrix.sync.aligned.m8n8.x4.shared.b16 {%0,%1,%2,%3}, [%4];"
                    : "=r"(af[i][0]), "=r"(af[i][1]), "=r"(af[i][2]), "=r"(af[i][3])
                    : "r"(addr));
            }
#pragma unroll
            for (int j = 0; j < 4; j++) {
                unsigned addr = b_base + so + j * 640 + kk * 32;
                asm volatile("ldmatrix.sync.aligned.m8n8.x2.shared.b16 {%0,%1}, [%2];"
                    : "=r"(bf[j][0]), "=r"(bf[j][1]) : "r"(addr));
            }
#pragma unroll
            for (int i = 0; i < 4; i++)
#pragma unroll
                for (int j = 0; j < 4; j++) {
                    asm volatile(
                        "mma.sync.aligned.m16n8k16.row.col.f32.bf16.bf16.f32 "
                        "{%0,%1,%2,%3}, {%4,%5,%6,%7}, {%8,%9}, {%0,%1,%2,%3};"
                        : "+f"(acc[i][j][0]), "+f"(acc[i][j][1]),
                          "+f"(acc[i][j][2]), "+f"(acc[i][j][3])
                        : "r"(af[i][0]), "r"(af[i][1]), "r"(af[i][2]), "r"(af[i][3]),
                          "r"(bf[j][0]), "r"(bf[j][1]));
                }
        }
        __syncthreads();
        st ^= 1;
    }

#pragma unroll
    for (int i = 0; i < 4; i++) {
        int mb = m0 + wm * 64 + i * 16 + (lane >> 2);
#pragma unroll
        for (int j = 0; j < 4; j++) {
            int nb = n0 + wn * 32 + j * 8 + (lane & 3) * 2;
            float bx = bias[nb], by = bias[nb + 1];
            float2 v0 = make_float2(acc[i][j][0] + bx, acc[i][j][1] + by);
            float2 v1 = make_float2(acc[i][j][2] + bx, acc[i][j][3] + by);
            if (relu) {
                v0.x = fmaxf(v0.x, 0.f); v0.y = fmaxf(v0.y, 0.f);
                v1.x = fmaxf(v1.x, 0.f); v1.y = fmaxf(v1.y, 0.f);
            }
            *(float2*)&C[(size_t)mb * N + nb]       = v0;
            *(float2*)&C[(size_t)(mb + 8) * N + nb] = v1;
        }
    }
}

// ---------------- persistent BiLSTM layer, tensor-core recurrence ----------------
// grid = 128 blocks (64 per dir), 256 threads (8 warps, 4x2 warp grid).
// Per step: h load (8 cp.async chunks of 16KB) overlapped with chunked MMA.
// Gates via separate smem f32 buffer. h bf16 in global, double-buffered by parity.
__global__ __launch_bounds__(256) void persist_lstm_tc(
    const float* __restrict__ xpf, const float* __restrict__ xpb,
    const float* __restrict__ whhf, const float* __restrict__ whhb,
    __nv_bfloat16* __restrict__ out)
{
    extern __shared__ __nv_bfloat16 smb[];
    __nv_bfloat16* hs = smb;                       // [128][520] bf16 (133120 B)
    __nv_bfloat16* ws = smb + 128 * 520;           // [32][520]  bf16 (33280 B)
    float* gsm = (float*)(smb + 128 * 520 + 32 * 520);  // [32][132] f32 (16896 B)

    int bid = blockIdx.x;
    int dir = bid >> 6;
    int j0 = (bid & 63) * 8;
    const float* xp  = dir ? xpb : xpf;
    const float* whh = dir ? whhb : whhf;

    int tid = threadIdx.x;
    int lane = tid & 31, wid = tid >> 5;
    int wm = wid >> 1, wn = wid & 1;               // 4x2 warp grid
    int jl = tid & 7, bg = tid >> 3;
    int b0v = bg * 4;
    int j = j0 + jl;

    // load Whh slice -> bf16 smem: row n = jl*4+g  <->  whh row (g*512 + j0 + jl)
#pragma unroll 4
    for (int it = 0; it < 64; it++) {
        int idx = it * 256 + tid;
        int n = idx >> 9, k = idx & 511;
        int grow = (n & 3) * Hn + j0 + (n >> 2);
        ws[n * 520 + k] = __float2bfloat16(whh[(size_t)grow * Hn + k]);
    }
    float c4[4] = {0.f, 0.f, 0.f, 0.f};
    __syncthreads();

    unsigned hs_u = (unsigned)__cvta_generic_to_shared(hs);
    unsigned ws_u = (unsigned)__cvta_generic_to_shared(ws);
    unsigned a_base = hs_u + ((wm * 32 + (lane & 15)) * 520 + (lane >> 4) * 8) * 2;
    unsigned b_base = ws_u + ((wn * 16 + (lane & 7)) * 520 + ((lane >> 3) & 1) * 8) * 2;

    for (int s = 0; s < Sn; s++) {
        int t = dir ? (Sn - 1 - s) : s;
        const __nv_bfloat16* hin = d_hstb[dir][s & 1];
        __nv_bfloat16* hout = d_hstb[dir][(s & 1) ^ 1];

        // issue h loads: 8 chunks x 16KB (64 k-cols each), one commit group each
#pragma unroll
        for (int ch = 0; ch < 8; ch++) {
#pragma unroll
            for (int it = 0; it < 4; it++) {
                int idx = it * 256 + tid;      // 0..1023
                int b = idx >> 3;
                int cq = idx & 7;
                cpasync16(hs_u + (b * 520 + ch * 64 + cq * 8) * 2,
                          hin + (size_t)b * Hn + ch * 64 + cq * 8);
            }
            cpcommit();
        }

        // prefetch xp gate pre-activations (overlaps with cp.async)
        float xr[4][4];
#pragma unroll
        for (int bi = 0; bi < 4; bi++) {
            size_t xb = ((size_t)t * Bn + b0v + bi) * G4n;
#pragma unroll
            for (int g = 0; g < 4; g++)
                xr[bi][g] = xp[xb + g * Hn + j];
        }

        float acc[2][2][4];
#pragma unroll
        for (int i = 0; i < 2; i++)
#pragma unroll
            for (int jt = 0; jt < 2; jt++)
#pragma unroll
                for (int r = 0; r < 4; r++) acc[i][jt][r] = 0.f;

        // consume chunks as they land
#pragma unroll
        for (int ch = 0; ch < 8; ch++) {
            if      (ch == 0) cpwait<7>();
            else if (ch == 1) cpwait<6>();
            else if (ch == 2) cpwait<5>();
            else if (ch == 3) cpwait<4>();
            else if (ch == 4) cpwait<3>();
            else if (ch == 5) cpwait<2>();
            else if (ch == 6) cpwait<1>();
            else              cpwait<0>();
            __syncthreads();
#pragma unroll
            for (int k2 = 0; k2 < 4; k2++) {
                int k = ch * 4 + k2;
                unsigned af[2][4], bfr[2][2];
#pragma unroll
                for (int i = 0; i < 2; i++) {
                    unsigned addr = a_base + i * (16 * 520 * 2) + k * 32;
                    asm volatile("ldmatrix.sync.aligned.m8n8.x4.shared.b16 {%0,%1,%2,%3}, [%4];"
                        : "=r"(af[i][0]), "=r"(af[i][1]), "=r"(af[i][2]), "=r"(af[i][3])
                        : "r"(addr));
                }
#pragma unroll
                for (int jt = 0; jt < 2; jt++) {
                    unsigned addr = b_base + jt * (8 * 520 * 2) + k * 32;
                    asm volatile("ldmatrix.sync.aligned.m8n8.x2.shared.b16 {%0,%1}, [%2];"
                        : "=r"(bfr[jt][0]), "=r"(bfr[jt][1]) : "r"(addr));
                }
#pragma unroll
                for (int i = 0; i < 2; i++)
#pragma unroll
                    for (int jt = 0; jt < 2; jt++) {
                        asm volatile(
                            "mma.sync.aligned.m16n8k16.row.col.f32.bf16.bf16.f32 "
                            "{%0,%1,%2,%3}, {%4,%5,%6,%7}, {%8,%9}, {%0,%1,%2,%3};"
                            : "+f"(acc[i][jt][0]), "+f"(acc[i][jt][1]),
                              "+f"(acc[i][jt][2]), "+f"(acc[i][jt][3])
                            : "r"(af[i][0]), "r"(af[i][1]), "r"(af[i][2]), "r"(af[i][3]),
                              "r"(bfr[jt][0]), "r"(bfr[jt][1]));
                    }
            }
        }

        // fragments -> gsm[n][b]  (separate buffer; prior-step reads fenced by barrier)
#pragma unroll
        for (int i = 0; i < 2; i++) {
            int m = wm * 32 + i * 16 + (lane >> 2);
#pragma unroll
            for (int jt = 0; jt < 2; jt++) {
                int n = wn * 16 + jt * 8 + (lane & 3) * 2;
                gsm[n * 132 + m]           = acc[i][jt][0];
                gsm[(n + 1) * 132 + m]     = acc[i][jt][1];
                gsm[n * 132 + m + 8]       = acc[i][jt][2];
                gsm[(n + 1) * 132 + m + 8] = acc[i][jt][3];
            }
        }
        __syncthreads();

        // epilogue: gates, activations, h/out stores
#pragma unroll
        for (int bi = 0; bi < 4; bi++) {
            int b = b0v + bi;
            float gi = gsm[(jl * 4 + 0) * 132 + b] + xr[bi][0];
            float gf = gsm[(jl * 4 + 1) * 132 + b] + xr[bi][1];
            float gg = gsm[(jl * 4 + 2) * 132 + b] + xr[bi][2];
            float go = gsm[(jl * 4 + 3) * 132 + b] + xr[bi][3];
            float ig = 1.f / (1.f + expf(-gi));
            float fg = 1.f / (1.f + expf(-gf));
            float og = 1.f / (1.f + expf(-go));
            float cc = fg * c4[bi] + ig * tanhf(gg);
            float hh = og * tanhf(cc);
            c4[bi] = cc;
            __nv_bfloat16 hb = __float2bfloat16(hh);
            hout[b * Hn + j] = hb;
            out[((size_t)t * Bn + b) * (2 * Hn) + dir * Hn + j] = hb;
        }

        // per-dir global barrier across the 64 blocks of this direction
        __syncthreads();
        if (tid == 0) {
            __threadfence();
            unsigned old = g_gen[dir];
            if (atomicAdd(&g_cnt[dir], 1u) == 63u) {
                g_cnt[dir] = 0;
                __threadfence();
                g_gen[dir] = old + 1u;
            } else {
                while (g_gen[dir] == old) { }
                __threadfence();
            }
        }
        __syncthreads();
    }
}

// ---------------- emissions: em[row][t] = hfc[row] . cls_w[t] + cls_b[t] ----------
__global__ void emissions_kernel(const float* __restrict__ hfc,
                                 const float* __restrict__ cls_w,
                                 const float* __restrict__ cls_b)
{
    int warp = blockIdx.x * 8 + (threadIdx.x >> 5);
    int lane = threadIdx.x & 31;
    const float* hrow = hfc + (size_t)warp * Hn;
    float hv[16];
#pragma unroll
    for (int q = 0; q < 16; q++) hv[q] = hrow[lane + q * 32];
    for (int tt = 0; tt < Tn; tt++) {
        const float* wr = cls_w + tt * Hn;
        float s = 0.f;
#pragma unroll
        for (int q = 0; q < 16; q++) s += hv[q] * wr[lane + q * 32];
#pragma unroll
        for (int o = 16; o > 0; o >>= 1) s += __shfl_xor_sync(0xffffffffu, s, o);
        if (lane == 0) d_em[(size_t)warp * Tn + tt] = s + cls_b[tt];
    }
}

// ---------------- CRF gold-path score (numerator) ----------------
__global__ void crf_num_kernel(const int* __restrict__ ids, const int* __restrict__ tags,
                               const float* __restrict__ trans,
                               const float* __restrict__ start_t, const float* __restrict__ end_t)
{
    int b = threadIdx.x;
    int tg0 = tags[b * Sn + 0];
    float score = start_t[tg0] + d_em[(size_t)b * Tn + tg0];
    int cnt = (ids[b * Sn + 0] != 0) ? 1 : 0;
    int prev = tg0;
    for (int s = 1; s < Sn; s++) {
        int tg = tags[b * Sn + s];
        if (ids[b * Sn + s] != 0) {
            score += trans[prev * Tn + tg] + d_em[((size_t)s * Bn + b) * Tn + tg];
            cnt++;
        }
        prev = tg;
    }
    int se = cnt - 1; if (se < 0) se = 0;
    d_num[b] = score + end_t[tags[b * Sn + se]];
}

// ---------------- CRF forward algorithm (denominator) ----------------
__global__ void crf_fwd_kernel(const int* __restrict__ ids,
                               const float* __restrict__ trans,
                               const float* __restrict__ start_t,
                               const float* __restrict__ end_t)
{
    int b = blockIdx.x;
    int j = threadIdx.x;
    __shared__ float alpha[Tn];
    __shared__ float tr[Tn * Tn];
    for (int idx = j; idx < Tn * Tn; idx += 32) tr[idx] = trans[idx];
    if (j < Tn) alpha[j] = start_t[j] + d_em[(size_t)b * Tn + j];
    __syncthreads();
    for (int s = 1; s < Sn; s++) {
        bool m = ids[b * Sn + s] != 0;
        float ns = 0.f;
        if (m && j < Tn) {
            float mx = -1e30f;
#pragma unroll
            for (int i = 0; i < Tn; i++) mx = fmaxf(mx, alpha[i] + tr[i * Tn + j]);
            float sum = 0.f;
#pragma unroll
            for (int i = 0; i < Tn; i++) sum += expf(alpha[i] + tr[i * Tn + j] - mx);
            ns = mx + logf(sum) + d_em[((size_t)s * Bn + b) * Tn + j];
        }
        __syncthreads();
        if (m && j < Tn) alpha[j] = ns;
        __syncthreads();
    }
    if (j == 0) {
        float mx = -1e30f;
        for (int i = 0; i < Tn; i++) mx = fmaxf(mx, alpha[i] + end_t[i]);
        float sum = 0.f;
        for (int i = 0; i < Tn; i++) sum += expf(alpha[i] + end_t[i] - mx);
        d_den[b] = mx + logf(sum);
    }
}

// ---------------- final: out = mean(num - den) ----------------
__global__ void final_kernel(float* __restrict__ out)
{
    int tid = threadIdx.x;
    __shared__ float sm[128];
    sm[tid] = d_num[tid] - d_den[tid];
    __syncthreads();
    for (int o = 64; o > 0; o >>= 1) {
        if (tid < o) sm[tid] += sm[tid + o];
        __syncthreads();
    }
    if (tid == 0) out[0] = sm[0] / 128.f;
}

// ---------------- launch ----------------
extern "C" void kernel_launch(void* const* d_in, const int* in_sizes, int n_in,
                              void* d_out, int out_size)
{
    (void)in_sizes; (void)n_in; (void)out_size;
    const int*   ids      = (const int*)d_in[0];
    const int*   tags     = (const int*)d_in[1];
    const float* emb      = (const float*)d_in[2];
    const float* w_ih_l0f = (const float*)d_in[3];
    const float* w_hh_l0f = (const float*)d_in[4];
    const float* b_l0f    = (const float*)d_in[5];
    const float* w_ih_l0b = (const float*)d_in[6];
    const float* w_hh_l0b = (const float*)d_in[7];
    const float* b_l0b    = (const float*)d_in[8];
    const float* w_ih_l1f = (const float*)d_in[9];
    const float* w_hh_l1f = (const float*)d_in[10];
    const float* b_l1f    = (const float*)d_in[11];
    const float* w_ih_l1b = (const float*)d_in[12];
    const float* w_hh_l1b = (const float*)d_in[13];
    const float* b_l1b    = (const float*)d_in[14];
    const float* fc_w     = (const float*)d_in[15];
    const float* fc_b     = (const float*)d_in[16];
    const float* cls_w    = (const float*)d_in[17];
    const float* cls_b    = (const float*)d_in[18];
    const float* trans    = (const float*)d_in[19];
    const float* start_t  = (const float*)d_in[20];
    const float* end_t    = (const float*)d_in[21];
    float* out = (float*)d_out;

    float *pxf, *pxb, *phfc;
    __nv_bfloat16 *pxbuf, *pout0b, *pout1b, *pw0f, *pw0b, *pw1f, *pw1b, *pwfc, *phstb;
    cudaGetSymbolAddress((void**)&pxbuf, d_xb);
    cudaGetSymbolAddress((void**)&pxf,   d_xp_f);
    cudaGetSymbolAddress((void**)&pxb,   d_xp_b);
    cudaGetSymbolAddress((void**)&pout0b, d_out0b);
    cudaGetSymbolAddress((void**)&pout1b, d_out1b);
    cudaGetSymbolAddress((void**)&phfc,  d_hfc);
    cudaGetSymbolAddress((void**)&phstb, d_hstb);
    cudaGetSymbolAddress((void**)&pw0f,  d_wb_l0f);
    cudaGetSymbolAddress((void**)&pw0b,  d_wb_l0b);
    cudaGetSymbolAddress((void**)&pw1f,  d_wb_l1f);
    cudaGetSymbolAddress((void**)&pw1b,  d_wb_l1b);
    cudaGetSymbolAddress((void**)&pwfc,  d_wb_fc);

    const int SMEM_LSTM = 128 * 520 * 2 + 32 * 520 * 2 + 32 * 132 * 4;  // 183296 B
    cudaFuncSetAttribute(persist_lstm_tc, cudaFuncAttributeMaxDynamicSharedMemorySize, SMEM_LSTM);

    // weight converts for the big GEMMs
    f2bf_kernel<<<(G4n * En / 4 + 255) / 256, 256>>>(w_ih_l0f, pw0f, G4n * En / 4);
    f2bf_kernel<<<(G4n * En / 4 + 255) / 256, 256>>>(w_ih_l0b, pw0b, G4n * En / 4);
    f2bf_kernel<<<(G4n * 2 * Hn / 4 + 255) / 256, 256>>>(w_ih_l1f, pw1f, G4n * 2 * Hn / 4);
    f2bf_kernel<<<(G4n * 2 * Hn / 4 + 255) / 256, 256>>>(w_ih_l1b, pw1b, G4n * 2 * Hn / 4);
    f2bf_kernel<<<(Hn * 2 * Hn / 4 + 255) / 256, 256>>>(fc_w, pwfc, Hn * 2 * Hn / 4);

    embed_kernel<<<Sn * Bn, 64>>>(ids, emb);

    // layer 0 input projections (row-major xp [t][b][g*512+j])
    dim3 g0(G4n / 128, (Sn * Bn) / 128);
    gemm_bf16<<<g0, 256>>>(pxbuf, pw0f, b_l0f, pxf, G4n, En, 0);
    gemm_bf16<<<g0, 256>>>(pxbuf, pw0b, b_l0b, pxb, G4n, En, 0);

    cudaMemsetAsync(phstb, 0, sizeof(d_hstb), 0);
    persist_lstm_tc<<<128, 256, SMEM_LSTM>>>(pxf, pxb, w_hh_l0f, w_hh_l0b, pout0b);

    // layer 1 input projections
    gemm_bf16<<<g0, 256>>>(pout0b, pw1f, b_l1f, pxf, G4n, 2 * Hn, 0);
    gemm_bf16<<<g0, 256>>>(pout0b, pw1b, b_l1b, pxb, G4n, 2 * Hn, 0);

    cudaMemsetAsync(phstb, 0, sizeof(d_hstb), 0);
    persist_lstm_tc<<<128, 256, SMEM_LSTM>>>(pxf, pxb, w_hh_l1f, w_hh_l1b, pout1b);

    // fc + relu
    dim3 gfc(Hn / 128, (Sn * Bn) / 128);
    gemm_bf16<<<gfc, 256>>>(pout1b, pwfc, fc_b, phfc, Hn, 2 * Hn, 1);

    emissions_kernel<<<(Sn * Bn) / 8, 256>>>(phfc, cls_w, cls_b);
    crf_num_kernel<<<1, Bn>>>(ids, tags, trans, start_t, end_t);
    crf_fwd_kernel<<<Bn, 32>>>(ids, trans, start_t, end_t);
    final_kernel<<<1, Bn>>>(out);
}